// round 1
// baseline (speedup 1.0000x reference)
#include <cuda_runtime.h>
#include <cuda_bf16.h>
#include <math.h>

// Problem constants
#define NTOK 4096          // B*T
#define CDIM 1024
#define HDIM 4096
#define NEXP 8
#define TOPK 2
#define NPAIR (NTOK * TOPK)   // 8192, always exactly N*K pairs

// ---------------- scratch (device globals; no allocations allowed) ----------
__device__ int   g_counts[NEXP];
__device__ int   g_cursor[NEXP];
__device__ int   g_offs[NEXP + 1];
__device__ int   g_topi[NPAIR];
__device__ float g_topw[NPAIR];
__device__ int   g_rows[NPAIR];   // compact slot -> token id
__device__ int   g_map[NPAIR];    // (token,k) -> compact slot
__device__ float g_h1[(size_t)NPAIR * HDIM];  // h1, then silu(h1)*h3 in place
__device__ float g_h3[(size_t)NPAIR * HDIM];
__device__ float g_y [(size_t)NPAIR * CDIM];

// ---------------- router: logits -> softmax -> top2 -> renorm ---------------
__global__ void router_kernel(const float* __restrict__ x,
                              const float* __restrict__ Wg) {
    const int n = blockIdx.x;
    const int t = threadIdx.x;
    float acc[NEXP];
#pragma unroll
    for (int e = 0; e < NEXP; e++) acc[e] = 0.f;
    const float* xr = x + (size_t)n * CDIM;
    for (int c = t; c < CDIM; c += 256) {
        float xv = xr[c];
        const float* wr = Wg + c * NEXP;
#pragma unroll
        for (int e = 0; e < NEXP; e++) acc[e] += xv * wr[e];
    }
#pragma unroll
    for (int off = 16; off; off >>= 1)
#pragma unroll
        for (int e = 0; e < NEXP; e++)
            acc[e] += __shfl_down_sync(0xffffffffu, acc[e], off);

    __shared__ float red[8][NEXP];
    if ((t & 31) == 0)
#pragma unroll
        for (int e = 0; e < NEXP; e++) red[t >> 5][e] = acc[e];
    __syncthreads();
    if (t == 0) {
        float l[NEXP];
#pragma unroll
        for (int e = 0; e < NEXP; e++) {
            float s = 0.f;
#pragma unroll
            for (int w = 0; w < 8; w++) s += red[w][e];   // fixed order: deterministic
            l[e] = s;
        }
        float mx = l[0];
#pragma unroll
        for (int e = 1; e < NEXP; e++) mx = fmaxf(mx, l[e]);
        float p[NEXP];
#pragma unroll
        for (int e = 0; e < NEXP; e++) p[e] = expf(l[e] - mx);
        int i0 = 0;
#pragma unroll
        for (int e = 1; e < NEXP; e++) if (p[e] > p[i0]) i0 = e;
        int i1 = (i0 == 0) ? 1 : 0;
#pragma unroll
        for (int e = 0; e < NEXP; e++) if (e != i0 && p[e] > p[i1]) i1 = e;
        float s = p[i0] + p[i1];
        g_topi[2 * n]     = i0;
        g_topi[2 * n + 1] = i1;
        g_topw[2 * n]     = p[i0] / s;   // softmax denom cancels in renorm
        g_topw[2 * n + 1] = p[i1] / s;
    }
}

// ---------------- routing bookkeeping ----------------------------------------
__global__ void zero_counts_kernel() {
    if (threadIdx.x < NEXP) g_counts[threadIdx.x] = 0;
}
__global__ void count_kernel() {
    int i = blockIdx.x * blockDim.x + threadIdx.x;
    if (i < NPAIR) atomicAdd(&g_counts[g_topi[i]], 1);
}
__global__ void offsets_kernel() {
    if (blockIdx.x == 0 && threadIdx.x == 0) {
        int s = 0;
        for (int e = 0; e < NEXP; e++) {
            g_offs[e] = s; g_cursor[e] = s; s += g_counts[e];
        }
        g_offs[NEXP] = s;   // == NPAIR
    }
}
__global__ void scatter_kernel() {
    int i = blockIdx.x * blockDim.x + threadIdx.x;
    if (i < NPAIR) {
        int e   = g_topi[i];
        int pos = atomicAdd(&g_cursor[e], 1);   // slot order nondeterministic,
        g_rows[pos] = i >> 1;                   // but per-row math is order-free
        g_map[i]    = pos;                      // -> output is deterministic
    }
}

// ---------------- split-bf16 grouped GEMM ------------------------------------
// C[slot, n] = A[row(slot), k] * B[e, k, n], fp32 in/out, hi/lo bf16 MMA.
#define TM 128
#define TN 128
#define TKK 16
#define SKP 18   // padded k-stride (conflict mitigation)

__device__ __forceinline__ void mma_bf16(float* d, const unsigned* a, const unsigned* b) {
    asm volatile(
        "mma.sync.aligned.m16n8k16.row.col.f32.bf16.bf16.f32 "
        "{%0,%1,%2,%3}, {%4,%5,%6,%7}, {%8,%9}, {%0,%1,%2,%3};\n"
        : "+f"(d[0]), "+f"(d[1]), "+f"(d[2]), "+f"(d[3])
        : "r"(a[0]), "r"(a[1]), "r"(a[2]), "r"(a[3]), "r"(b[0]), "r"(b[1]));
}

// OUTSEL: 0 -> g_h1, 1 -> g_h3, 2 -> g_y.  GATHER: A rows via g_rows (from x).
template <bool GATHER, int OUTSEL>
__global__ __launch_bounds__(256) void gemm_split(
    const float* __restrict__ Aparam,   // x (GATHER) ; ignored otherwise
    const float* __restrict__ Bbase,    // [E][Kdim][Ndim]
    int Kdim, int Ndim)
{
    __shared__ __nv_bfloat16 AsH[TM][SKP], AsL[TM][SKP];
    __shared__ __nv_bfloat16 BsH[TN][SKP], BsL[TN][SKP];
    __shared__ int srow[TM];

    const int e    = blockIdx.z;
    const int cnt  = g_counts[e];
    const int row0 = blockIdx.y * TM;
    if (row0 >= cnt) return;
    const int mrows    = min(TM, cnt - row0);
    const int slotbase = g_offs[e] + row0;
    const int nt0      = blockIdx.x * TN;
    const float* Bexp  = Bbase + (size_t)e * Kdim * Ndim;
    const float* Abase = GATHER ? Aparam : g_h1;
    float* Cbase = (OUTSEL == 0) ? g_h1 : (OUTSEL == 1) ? g_h3 : g_y;

    const int t = threadIdx.x;
    if (t < TM) {
        int m = (t < mrows) ? t : 0;   // clamp ragged tail to a valid row
        srow[t] = GATHER ? g_rows[slotbase + m] : (slotbase + m);
    }
    __syncthreads();

    const int lane = t & 31;
    const int warp = t >> 5;
    const int wm = (warp & 3) * 32;
    const int wn = (warp >> 2) * 64;
    const int g  = lane >> 2;
    const int q  = lane & 3;

    float acc[2][8][4];
#pragma unroll
    for (int mi = 0; mi < 2; mi++)
#pragma unroll
        for (int ni = 0; ni < 8; ni++)
#pragma unroll
            for (int j = 0; j < 4; j++) acc[mi][ni][j] = 0.f;

    const int am = t >> 2;            // 0..63 (A row / pass)
    const int ak = (t & 3) << 2;      // 0,4,8,12
    const int bk = t >> 4;            // 0..15 (B k-row)
    const int bn = (t & 15) << 2;     // 0..60

    const float* arow0 = Abase + (size_t)srow[am]      * Kdim;
    const float* arow1 = Abase + (size_t)srow[am + 64] * Kdim;

    float4 pa[2], pb[2];
    auto gload = [&](int k0) {
        pa[0] = *(const float4*)(arow0 + k0 + ak);
        pa[1] = *(const float4*)(arow1 + k0 + ak);
        const float* bp = Bexp + (size_t)(k0 + bk) * Ndim + nt0 + bn;
        pb[0] = *(const float4*)(bp);
        pb[1] = *(const float4*)(bp + 64);
    };
    auto sstore = [&]() {
#pragma unroll
        for (int p = 0; p < 2; p++) {
            float va[4] = {pa[p].x, pa[p].y, pa[p].z, pa[p].w};
            int m = am + p * 64;
#pragma unroll
            for (int j = 0; j < 4; j++) {
                __nv_bfloat16 h = __float2bfloat16(va[j]);
                __nv_bfloat16 l = __float2bfloat16(va[j] - __bfloat162float(h));
                AsH[m][ak + j] = h;
                AsL[m][ak + j] = l;
            }
            float vb[4] = {pb[p].x, pb[p].y, pb[p].z, pb[p].w};
#pragma unroll
            for (int j = 0; j < 4; j++) {
                __nv_bfloat16 h = __float2bfloat16(vb[j]);
                __nv_bfloat16 l = __float2bfloat16(vb[j] - __bfloat162float(h));
                BsH[bn + p * 64 + j][bk] = h;   // stored [n][k]
                BsL[bn + p * 64 + j][bk] = l;
            }
        }
    };

    gload(0);
    sstore();
    __syncthreads();

    for (int k0 = 0; k0 < Kdim; k0 += TKK) {
        const bool more = (k0 + TKK < Kdim);
        if (more) gload(k0 + TKK);   // overlap gmem with MMA

        unsigned ah[2][4], al[2][4], bh[8][2], bl[8][2];
#pragma unroll
        for (int mi = 0; mi < 2; mi++) {
            int r = wm + mi * 16 + g;
            ah[mi][0] = *(const unsigned*)&AsH[r][q * 2];
            ah[mi][1] = *(const unsigned*)&AsH[r + 8][q * 2];
            ah[mi][2] = *(const unsigned*)&AsH[r][q * 2 + 8];
            ah[mi][3] = *(const unsigned*)&AsH[r + 8][q * 2 + 8];
            al[mi][0] = *(const unsigned*)&AsL[r][q * 2];
            al[mi][1] = *(const unsigned*)&AsL[r + 8][q * 2];
            al[mi][2] = *(const unsigned*)&AsL[r][q * 2 + 8];
            al[mi][3] = *(const unsigned*)&AsL[r + 8][q * 2 + 8];
        }
#pragma unroll
        for (int ni = 0; ni < 8; ni++) {
            int r = wn + ni * 8 + g;
            bh[ni][0] = *(const unsigned*)&BsH[r][q * 2];
            bh[ni][1] = *(const unsigned*)&BsH[r][q * 2 + 8];
            bl[ni][0] = *(const unsigned*)&BsL[r][q * 2];
            bl[ni][1] = *(const unsigned*)&BsL[r][q * 2 + 8];
        }
#pragma unroll
        for (int mi = 0; mi < 2; mi++)
#pragma unroll
            for (int ni = 0; ni < 8; ni++) {
                mma_bf16(acc[mi][ni], ah[mi], bh[ni]);  // hi*hi
                mma_bf16(acc[mi][ni], al[mi], bh[ni]);  // lo*hi
                mma_bf16(acc[mi][ni], ah[mi], bl[ni]);  // hi*lo
            }
        __syncthreads();
        if (more) {
            sstore();
            __syncthreads();
        }
    }

    // epilogue (fp32 store, ragged m guard)
#pragma unroll
    for (int mi = 0; mi < 2; mi++)
#pragma unroll
        for (int ni = 0; ni < 8; ni++) {
            int r0 = wm + mi * 16 + g;
            int c  = nt0 + wn + ni * 8 + q * 2;
            float* crow = Cbase + (size_t)(slotbase + r0) * Ndim + c;
            if (r0 < mrows) {
                crow[0] = acc[mi][ni][0];
                crow[1] = acc[mi][ni][1];
            }
            if (r0 + 8 < mrows) {
                float* crow2 = crow + (size_t)8 * Ndim;
                crow2[0] = acc[mi][ni][2];
                crow2[1] = acc[mi][ni][3];
            }
        }
}

// ---------------- SwiGLU elementwise (in place into g_h1) -------------------
__global__ void silu_mul_kernel() {
    size_t i = ((size_t)blockIdx.x * blockDim.x + threadIdx.x) << 2;
    float4 a = *(const float4*)(g_h1 + i);
    float4 b = *(const float4*)(g_h3 + i);
    a.x = a.x / (1.f + expf(-a.x)) * b.x;
    a.y = a.y / (1.f + expf(-a.y)) * b.y;
    a.z = a.z / (1.f + expf(-a.z)) * b.z;
    a.w = a.w / (1.f + expf(-a.w)) * b.w;
    *(float4*)(g_h1 + i) = a;
}

// ---------------- final gather-combine --------------------------------------
__global__ void combine_kernel(float* __restrict__ out) {
    int idx = blockIdx.x * blockDim.x + threadIdx.x;   // NTOK * 256 threads
    int n  = idx >> 8;
    int c4 = (idx & 255) << 2;
    int p0 = g_map[2 * n], p1 = g_map[2 * n + 1];
    float w0 = g_topw[2 * n], w1 = g_topw[2 * n + 1];
    float4 y0 = *(const float4*)(g_y + (size_t)p0 * CDIM + c4);
    float4 y1 = *(const float4*)(g_y + (size_t)p1 * CDIM + c4);
    float4 r;
    r.x = w0 * y0.x + w1 * y1.x;
    r.y = w0 * y0.y + w1 * y1.y;
    r.z = w0 * y0.z + w1 * y1.z;
    r.w = w0 * y0.w + w1 * y1.w;
    *(float4*)(out + (size_t)n * CDIM + c4) = r;
}

// ---------------- launch ------------------------------------------------------
extern "C" void kernel_launch(void* const* d_in, const int* in_sizes, int n_in,
                              void* d_out, int out_size) {
    const float* x  = (const float*)d_in[0];
    const float* Wg = (const float*)d_in[1];
    const float* W1 = (const float*)d_in[2];
    const float* W3 = (const float*)d_in[3];
    const float* W2 = (const float*)d_in[4];
    float* out = (float*)d_out;

    router_kernel<<<NTOK, 256>>>(x, Wg);
    zero_counts_kernel<<<1, 32>>>();
    count_kernel<<<NPAIR / 256, 256>>>();
    offsets_kernel<<<1, 1>>>();
    scatter_kernel<<<NPAIR / 256, 256>>>();

    // h1 = Xg @ W1 ; h3 = Xg @ W3   (per-expert, gathered rows of x)
    gemm_split<true, 0><<<dim3(HDIM / TN, NTOK / TM, NEXP), 256>>>(x, W1, CDIM, HDIM);
    gemm_split<true, 1><<<dim3(HDIM / TN, NTOK / TM, NEXP), 256>>>(x, W3, CDIM, HDIM);

    // hidden = silu(h1) * h3  (in place into g_h1)
    silu_mul_kernel<<<((size_t)NPAIR * HDIM / 4) / 256, 256>>>();

    // y = hidden @ W2  (per-expert)
    gemm_split<false, 2><<<dim3(CDIM / TN, NTOK / TM, NEXP), 256>>>(nullptr, W2, HDIM, CDIM);

    combine_kernel<<<(NTOK * (CDIM / 4)) / 256, 256>>>(out);
}

// round 2
// speedup vs baseline: 1.0914x; 1.0914x over previous
#include <cuda_runtime.h>
#include <cuda_bf16.h>
#include <math.h>

// Problem constants
#define NTOK 4096          // B*T
#define CDIM 1024
#define HDIM 4096
#define NEXP 8
#define NPAIR (NTOK * 2)   // top-2 pairs

// ---------------- scratch (device globals; no allocations allowed) ----------
__device__ int   g_counts[NEXP];
__device__ int   g_offs[NEXP + 1];
__device__ int   g_topi[NPAIR];
__device__ float g_topw[NPAIR];
__device__ int   g_rows[NPAIR];   // compact slot -> token id
__device__ int   g_map[NPAIR];    // (token,k) -> compact slot
__device__ __nv_bfloat16 g_xh[(size_t)NTOK * CDIM];   // x split planes
__device__ __nv_bfloat16 g_xl[(size_t)NTOK * CDIM];
__device__ float g_h1[(size_t)NPAIR * HDIM];
__device__ float g_h3[(size_t)NPAIR * HDIM];
__device__ __nv_bfloat16 g_hh[(size_t)NPAIR * HDIM];  // hidden split planes
__device__ __nv_bfloat16 g_hl[(size_t)NPAIR * HDIM];
__device__ float g_y [(size_t)NPAIR * CDIM];

// ---------------- router ------------------------------------------------------
__global__ void router_kernel(const float* __restrict__ x,
                              const float* __restrict__ Wg) {
    const int n = blockIdx.x;
    const int t = threadIdx.x;
    float acc[NEXP];
#pragma unroll
    for (int e = 0; e < NEXP; e++) acc[e] = 0.f;
    const float* xr = x + (size_t)n * CDIM;
    for (int c = t; c < CDIM; c += 256) {
        float xv = xr[c];
        const float* wr = Wg + c * NEXP;
#pragma unroll
        for (int e = 0; e < NEXP; e++) acc[e] += xv * wr[e];
    }
#pragma unroll
    for (int off = 16; off; off >>= 1)
#pragma unroll
        for (int e = 0; e < NEXP; e++)
            acc[e] += __shfl_down_sync(0xffffffffu, acc[e], off);

    __shared__ float red[8][NEXP];
    if ((t & 31) == 0)
#pragma unroll
        for (int e = 0; e < NEXP; e++) red[t >> 5][e] = acc[e];
    __syncthreads();
    if (t == 0) {
        float l[NEXP];
#pragma unroll
        for (int e = 0; e < NEXP; e++) {
            float s = 0.f;
#pragma unroll
            for (int w = 0; w < 8; w++) s += red[w][e];   // fixed order
            l[e] = s;
        }
        float mx = l[0];
#pragma unroll
        for (int e = 1; e < NEXP; e++) mx = fmaxf(mx, l[e]);
        float p[NEXP];
#pragma unroll
        for (int e = 0; e < NEXP; e++) p[e] = expf(l[e] - mx);
        int i0 = 0;
#pragma unroll
        for (int e = 1; e < NEXP; e++) if (p[e] > p[i0]) i0 = e;
        int i1 = (i0 == 0) ? 1 : 0;
#pragma unroll
        for (int e = 0; e < NEXP; e++) if (e != i0 && p[e] > p[i1]) i1 = e;
        float s = p[i0] + p[i1];
        g_topi[2 * n]     = i0;
        g_topi[2 * n + 1] = i1;
        g_topw[2 * n]     = p[i0] / s;
        g_topw[2 * n + 1] = p[i1] / s;
    }
}

// ---------------- fused routing bookkeeping (one block) ----------------------
__global__ void route_build_kernel() {
    __shared__ int cnt[NEXP], cur[NEXP];
    const int t = threadIdx.x;           // 1024 threads
    if (t < NEXP) cnt[t] = 0;
    __syncthreads();
    for (int i = t; i < NPAIR; i += 1024) atomicAdd(&cnt[g_topi[i]], 1);
    __syncthreads();
    if (t == 0) {
        int s = 0;
        for (int e = 0; e < NEXP; e++) {
            g_counts[e] = cnt[e];
            g_offs[e] = s; cur[e] = s; s += cnt[e];
        }
        g_offs[NEXP] = s;
    }
    __syncthreads();
    for (int i = t; i < NPAIR; i += 1024) {
        int e = g_topi[i];
        int pos = atomicAdd(&cur[e], 1);  // order-free per-row math -> deterministic
        g_rows[pos] = i >> 1;
        g_map[i]    = pos;
    }
}

// ---------------- split helpers ----------------------------------------------
__device__ __forceinline__ void split_bf16(float v, unsigned short& h, unsigned short& l) {
    __nv_bfloat16 hb = __float2bfloat16(v);
    __nv_bfloat16 lb = __float2bfloat16(v - __bfloat162float(hb));
    h = __bfloat16_as_ushort(hb);
    l = __bfloat16_as_ushort(lb);
}

// x -> (xh, xl) bf16 planes
__global__ void xsplit_kernel(const float* __restrict__ x) {
    size_t idx = (size_t)blockIdx.x * blockDim.x + threadIdx.x;   // 4M/4 threads
    const float4 v = ((const float4*)x)[idx];
    unsigned short h[4], l[4];
    split_bf16(v.x, h[0], l[0]); split_bf16(v.y, h[1], l[1]);
    split_bf16(v.z, h[2], l[2]); split_bf16(v.w, h[3], l[3]);
    uint2 hp, lp;
    hp.x = (unsigned)h[0] | ((unsigned)h[1] << 16);
    hp.y = (unsigned)h[2] | ((unsigned)h[3] << 16);
    lp.x = (unsigned)l[0] | ((unsigned)l[1] << 16);
    lp.y = (unsigned)l[2] | ((unsigned)l[3] << 16);
    ((uint2*)g_xh)[idx] = hp;
    ((uint2*)g_xl)[idx] = lp;
}

// hidden = silu(h1)*h3 -> (hh, hl) bf16 planes
__global__ void silu_split_kernel() {
    size_t idx = (size_t)blockIdx.x * blockDim.x + threadIdx.x;   // 32M/4 threads
    float4 a = ((const float4*)g_h1)[idx];
    float4 b = ((const float4*)g_h3)[idx];
    float v[4];
    v[0] = a.x / (1.f + __expf(-a.x)) * b.x;
    v[1] = a.y / (1.f + __expf(-a.y)) * b.y;
    v[2] = a.z / (1.f + __expf(-a.z)) * b.z;
    v[3] = a.w / (1.f + __expf(-a.w)) * b.w;
    unsigned short h[4], l[4];
#pragma unroll
    for (int j = 0; j < 4; j++) split_bf16(v[j], h[j], l[j]);
    uint2 hp, lp;
    hp.x = (unsigned)h[0] | ((unsigned)h[1] << 16);
    hp.y = (unsigned)h[2] | ((unsigned)h[3] << 16);
    lp.x = (unsigned)l[0] | ((unsigned)l[1] << 16);
    lp.y = (unsigned)l[2] | ((unsigned)l[3] << 16);
    ((uint2*)g_hh)[idx] = hp;
    ((uint2*)g_hl)[idx] = lp;
}

// ---------------- split-bf16 tensor-core grouped GEMM ------------------------
#define TM 128
#define TN 128
#define TK 32
#define ASTR 40    // A row stride (bf16 elems): 80B -> conflict-free ldmatrix
#define BSTR 136   // B row stride: 272B -> conflict-free ldmatrix

struct SmemT {
    __nv_bfloat16 Ah[2][TM][ASTR];
    __nv_bfloat16 Al[2][TM][ASTR];
    __nv_bfloat16 Bh[2][TK][BSTR];
    __nv_bfloat16 Bl[2][TK][BSTR];
    int srow[TM];
};
#define AL_OFF (2 * TM * ASTR * 2)     // bytes from Ah[s][r][c] to Al[s][r][c]
#define BL_OFF (2 * TK * BSTR * 2)
#define SMEM_BYTES (sizeof(SmemT))

__device__ __forceinline__ unsigned sm_u32(const void* p) {
    return (unsigned)__cvta_generic_to_shared(p);
}
__device__ __forceinline__ void cp16(unsigned s, const void* g) {
    asm volatile("cp.async.ca.shared.global [%0], [%1], 16;\n" :: "r"(s), "l"(g));
}
__device__ __forceinline__ void ldsm4(unsigned* r, unsigned a) {
    asm volatile("ldmatrix.sync.aligned.m8n8.x4.shared.b16 {%0,%1,%2,%3}, [%4];"
                 : "=r"(r[0]), "=r"(r[1]), "=r"(r[2]), "=r"(r[3]) : "r"(a));
}
__device__ __forceinline__ void ldsm4t(unsigned* r, unsigned a) {
    asm volatile("ldmatrix.sync.aligned.m8n8.x4.trans.shared.b16 {%0,%1,%2,%3}, [%4];"
                 : "=r"(r[0]), "=r"(r[1]), "=r"(r[2]), "=r"(r[3]) : "r"(a));
}
__device__ __forceinline__ void mma_bf16(float* d, const unsigned* a, const unsigned* b) {
    asm volatile(
        "mma.sync.aligned.m16n8k16.row.col.f32.bf16.bf16.f32 "
        "{%0,%1,%2,%3}, {%4,%5,%6,%7}, {%8,%9}, {%0,%1,%2,%3};\n"
        : "+f"(d[0]), "+f"(d[1]), "+f"(d[2]), "+f"(d[3])
        : "r"(a[0]), "r"(a[1]), "r"(a[2]), "r"(a[3]), "r"(b[0]), "r"(b[1]));
}

// MODE 0: xh/xl (gather) x W1 -> g_h1 ; MODE 1: -> g_h3 (W3) ; MODE 2: hh/hl x W2 -> g_y
template <int MODE>
__global__ __launch_bounds__(256) void gemm_tc(const float* __restrict__ Bbase) {
    constexpr int Kd = (MODE == 2) ? HDIM : CDIM;
    constexpr int Nd = (MODE == 2) ? CDIM : HDIM;
    extern __shared__ char sm_raw[];
    SmemT& S = *reinterpret_cast<SmemT*>(sm_raw);

    const int e    = blockIdx.z;
    const int cnt  = g_counts[e];
    const int row0 = blockIdx.y * TM;
    if (row0 >= cnt) return;
    const int mrows    = min(TM, cnt - row0);
    const int slotbase = g_offs[e] + row0;
    const int nt0      = blockIdx.x * TN;
    const float* Bexp  = Bbase + (size_t)e * Kd * Nd;
    const __nv_bfloat16* Ahg = (MODE < 2) ? g_xh : g_hh;
    const __nv_bfloat16* Alg = (MODE < 2) ? g_xl : g_hl;
    float* Cb = (MODE == 0) ? g_h1 : (MODE == 1) ? g_h3 : g_y;

    const int t = threadIdx.x;
    if (t < TM) {
        int m = min(t, mrows - 1);
        S.srow[t] = (MODE < 2) ? g_rows[slotbase + m] : (slotbase + m);
    }
    __syncthreads();

    const int lane = t & 31;
    const int warp = t >> 5;
    const int wm = (warp & 3) * 32;
    const int wn = (warp >> 2) * 64;

    // producer indices
    const int ar = t >> 1;                  // A row 0..127
    const int ac = (t & 1) * 16;            // A col 0 or 16
    const long myrow = S.srow[ar];
    const __nv_bfloat16* gah = Ahg + myrow * Kd + ac;
    const __nv_bfloat16* gal = Alg + myrow * Kd + ac;
    const int bkr = t >> 3;                 // B k-row 0..31
    const int bnc = (t & 7) * 16;           // B n base (16 elems)
    const float* bgp = Bexp + (size_t)bkr * Nd + nt0 + bnc;

    float acc[2][8][4];
#pragma unroll
    for (int mi = 0; mi < 2; mi++)
#pragma unroll
        for (int ni = 0; ni < 8; ni++)
#pragma unroll
            for (int j = 0; j < 4; j++) acc[mi][ni][j] = 0.f;

    float bf[16];
    auto loadA = [&](int s, int k0) {
        unsigned sa = sm_u32(&S.Ah[s][ar][ac]);
        cp16(sa,          gah + k0);
        cp16(sa + 16,     gah + k0 + 8);
        cp16(sa + AL_OFF,      gal + k0);
        cp16(sa + AL_OFF + 16, gal + k0 + 8);
        asm volatile("cp.async.commit_group;\n");
    };
    auto loadB = [&](int k0) {
        const float4* p = (const float4*)(bgp + (size_t)k0 * Nd);
#pragma unroll
        for (int j = 0; j < 4; j++) {
            float4 v = p[j];
            bf[4 * j] = v.x; bf[4 * j + 1] = v.y; bf[4 * j + 2] = v.z; bf[4 * j + 3] = v.w;
        }
    };
    auto storeB = [&](int s) {
        unsigned short h[16], l[16];
#pragma unroll
        for (int j = 0; j < 16; j++) split_bf16(bf[j], h[j], l[j]);
        uint4 u0, u1, v0, v1;
        u0.x = h[0] | (h[1] << 16);  u0.y = h[2] | (h[3] << 16);
        u0.z = h[4] | (h[5] << 16);  u0.w = h[6] | (h[7] << 16);
        u1.x = h[8] | (h[9] << 16);  u1.y = h[10] | (h[11] << 16);
        u1.z = h[12] | (h[13] << 16); u1.w = h[14] | (h[15] << 16);
        v0.x = l[0] | (l[1] << 16);  v0.y = l[2] | (l[3] << 16);
        v0.z = l[4] | (l[5] << 16);  v0.w = l[6] | (l[7] << 16);
        v1.x = l[8] | (l[9] << 16);  v1.y = l[10] | (l[11] << 16);
        v1.z = l[12] | (l[13] << 16); v1.w = l[14] | (l[15] << 16);
        char* bh = (char*)&S.Bh[s][bkr][bnc];
        *(uint4*)bh = u0;
        *(uint4*)(bh + 16) = u1;
        *(uint4*)(bh + BL_OFF) = v0;
        *(uint4*)(bh + BL_OFF + 16) = v1;
    };

    auto compute = [&](int s) {
#pragma unroll
        for (int kk = 0; kk < 32; kk += 16) {
            unsigned ah[2][4], al[2][4], bh[8][2], bl[8][2];
#pragma unroll
            for (int mh = 0; mh < 2; mh++) {
                unsigned a = sm_u32(&S.Ah[s][wm + mh * 16 + (lane & 15)][kk + (lane >> 4) * 8]);
                ldsm4(ah[mh], a);
                ldsm4(al[mh], a + AL_OFF);
            }
#pragma unroll
            for (int ng = 0; ng < 4; ng++) {
                unsigned a = sm_u32(&S.Bh[s][kk + (lane & 15)][wn + ng * 16 + (lane >> 4) * 8]);
                unsigned r[4], q[4];
                ldsm4t(r, a);
                ldsm4t(q, a + BL_OFF);
                bh[2 * ng][0] = r[0]; bh[2 * ng][1] = r[1];
                bh[2 * ng + 1][0] = r[2]; bh[2 * ng + 1][1] = r[3];
                bl[2 * ng][0] = q[0]; bl[2 * ng][1] = q[1];
                bl[2 * ng + 1][0] = q[2]; bl[2 * ng + 1][1] = q[3];
            }
            // term-major: 16 independent accumulators between dependent reuses
#pragma unroll
            for (int mh = 0; mh < 2; mh++)
#pragma unroll
                for (int nf = 0; nf < 8; nf++) mma_bf16(acc[mh][nf], ah[mh], bh[nf]);
#pragma unroll
            for (int mh = 0; mh < 2; mh++)
#pragma unroll
                for (int nf = 0; nf < 8; nf++) mma_bf16(acc[mh][nf], al[mh], bh[nf]);
#pragma unroll
            for (int mh = 0; mh < 2; mh++)
#pragma unroll
                for (int nf = 0; nf < 8; nf++) mma_bf16(acc[mh][nf], ah[mh], bl[nf]);
        }
    };

    // prologue: stage 0
    loadA(0, 0);
    loadB(0);
    storeB(0);
    asm volatile("cp.async.wait_group 0;\n");
    __syncthreads();

#pragma unroll 1
    for (int k0 = 0;; k0 += TK) {
        const int s = (k0 >> 5) & 1;
        const bool more = (k0 + TK) < Kd;
        if (more) {
            loadA(s ^ 1, k0 + TK);
            loadB(k0 + TK);
        }
        compute(s);
        if (more) {
            storeB(s ^ 1);
            asm volatile("cp.async.wait_group 0;\n");
        }
        __syncthreads();
        if (!more) break;
    }

    // epilogue
    const int g = lane >> 2;
    const int q = lane & 3;
#pragma unroll
    for (int mh = 0; mh < 2; mh++)
#pragma unroll
        for (int nf = 0; nf < 8; nf++) {
            int r0 = wm + mh * 16 + g;
            int c  = nt0 + wn + nf * 8 + q * 2;
            float* crow = Cb + (size_t)(slotbase + r0) * Nd + c;
            if (r0 < mrows) {
                crow[0] = acc[mh][nf][0];
                crow[1] = acc[mh][nf][1];
            }
            if (r0 + 8 < mrows) {
                float* crow2 = crow + (size_t)8 * Nd;
                crow2[0] = acc[mh][nf][2];
                crow2[1] = acc[mh][nf][3];
            }
        }
}

// ---------------- final gather-combine --------------------------------------
__global__ void combine_kernel(float* __restrict__ out) {
    int idx = blockIdx.x * blockDim.x + threadIdx.x;
    int n  = idx >> 8;
    int c4 = (idx & 255) << 2;
    int p0 = g_map[2 * n], p1 = g_map[2 * n + 1];
    float w0 = g_topw[2 * n], w1 = g_topw[2 * n + 1];
    float4 y0 = *(const float4*)(g_y + (size_t)p0 * CDIM + c4);
    float4 y1 = *(const float4*)(g_y + (size_t)p1 * CDIM + c4);
    float4 r;
    r.x = w0 * y0.x + w1 * y1.x;
    r.y = w0 * y0.y + w1 * y1.y;
    r.z = w0 * y0.z + w1 * y1.z;
    r.w = w0 * y0.w + w1 * y1.w;
    *(float4*)(out + (size_t)n * CDIM + c4) = r;
}

// ---------------- launch ------------------------------------------------------
extern "C" void kernel_launch(void* const* d_in, const int* in_sizes, int n_in,
                              void* d_out, int out_size) {
    const float* x  = (const float*)d_in[0];
    const float* Wg = (const float*)d_in[1];
    const float* W1 = (const float*)d_in[2];
    const float* W3 = (const float*)d_in[3];
    const float* W2 = (const float*)d_in[4];
    float* out = (float*)d_out;

    cudaFuncSetAttribute(gemm_tc<0>, cudaFuncAttributeMaxDynamicSharedMemorySize, SMEM_BYTES);
    cudaFuncSetAttribute(gemm_tc<1>, cudaFuncAttributeMaxDynamicSharedMemorySize, SMEM_BYTES);
    cudaFuncSetAttribute(gemm_tc<2>, cudaFuncAttributeMaxDynamicSharedMemorySize, SMEM_BYTES);

    router_kernel<<<NTOK, 256>>>(x, Wg);
    route_build_kernel<<<1, 1024>>>();
    xsplit_kernel<<<(NTOK * CDIM / 4) / 256, 256>>>(x);

    gemm_tc<0><<<dim3(HDIM / TN, NTOK / TM, NEXP), 256, SMEM_BYTES>>>(W1);
    gemm_tc<1><<<dim3(HDIM / TN, NTOK / TM, NEXP), 256, SMEM_BYTES>>>(W3);

    silu_split_kernel<<<((size_t)NPAIR * HDIM / 4) / 256, 256>>>();

    gemm_tc<2><<<dim3(CDIM / TN, NTOK / TM, NEXP), 256, SMEM_BYTES>>>(W2);

    combine_kernel<<<(NTOK * (CDIM / 4)) / 256, 256>>>(out);
}

// round 5
// speedup vs baseline: 1.1280x; 1.0335x over previous
#include <cuda_runtime.h>
#include <cuda_bf16.h>
#include <math.h>

#define NTOK 4096
#define CDIM 1024
#define HDIM 4096
#define NEXP 8
#define NPAIR (NTOK * 2)

// ---------------- scratch (device globals) -----------------------------------
__device__ int   g_counts[NEXP];
__device__ int   g_offs[NEXP + 1];
__device__ int   g_topi[NPAIR];
__device__ float g_topw[NPAIR];
__device__ int   g_rows[NPAIR];
__device__ int   g_map[NPAIR];
__device__ __nv_bfloat16 g_xh[(size_t)NTOK * CDIM];
__device__ __nv_bfloat16 g_xl[(size_t)NTOK * CDIM];
__device__ float g_h1[(size_t)NPAIR * HDIM];
__device__ __nv_bfloat16 g_hh[(size_t)NPAIR * HDIM];
__device__ __nv_bfloat16 g_hl[(size_t)NPAIR * HDIM];
__device__ float g_y [(size_t)NPAIR * CDIM];
// weight planes, native [E][K][N] layout (N contiguous), bf16 hi/lo
__device__ __nv_bfloat16 g_w1h[(size_t)NEXP * CDIM * HDIM];
__device__ __nv_bfloat16 g_w1l[(size_t)NEXP * CDIM * HDIM];
__device__ __nv_bfloat16 g_w3h[(size_t)NEXP * CDIM * HDIM];
__device__ __nv_bfloat16 g_w3l[(size_t)NEXP * CDIM * HDIM];
__device__ __nv_bfloat16 g_w2h[(size_t)NEXP * HDIM * CDIM];
__device__ __nv_bfloat16 g_w2l[(size_t)NEXP * HDIM * CDIM];

// ---------------- helpers -----------------------------------------------------
__device__ __forceinline__ unsigned sm_u32(const void* p) {
    return (unsigned)__cvta_generic_to_shared(p);
}
__device__ __forceinline__ void cp16(unsigned s, const void* g) {
    asm volatile("cp.async.cg.shared.global [%0], [%1], 16;\n" :: "r"(s), "l"(g));
}
#define CP_COMMIT() asm volatile("cp.async.commit_group;" ::: "memory")
#define CP_WAIT1()  asm volatile("cp.async.wait_group 1;" ::: "memory")
#define CP_WAIT0()  asm volatile("cp.async.wait_group 0;" ::: "memory")
__device__ __forceinline__ void ldsm4(unsigned* r, unsigned a) {
    asm volatile("ldmatrix.sync.aligned.m8n8.x4.shared.b16 {%0,%1,%2,%3}, [%4];"
                 : "=r"(r[0]), "=r"(r[1]), "=r"(r[2]), "=r"(r[3]) : "r"(a));
}
__device__ __forceinline__ void ldsm4t(unsigned* r, unsigned a) {
    asm volatile("ldmatrix.sync.aligned.m8n8.x4.trans.shared.b16 {%0,%1,%2,%3}, [%4];"
                 : "=r"(r[0]), "=r"(r[1]), "=r"(r[2]), "=r"(r[3]) : "r"(a));
}
__device__ __forceinline__ void mma_bf16(float* d, const unsigned* a, const unsigned* b) {
    asm volatile(
        "mma.sync.aligned.m16n8k16.row.col.f32.bf16.bf16.f32 "
        "{%0,%1,%2,%3}, {%4,%5,%6,%7}, {%8,%9}, {%0,%1,%2,%3};\n"
        : "+f"(d[0]), "+f"(d[1]), "+f"(d[2]), "+f"(d[3])
        : "r"(a[0]), "r"(a[1]), "r"(a[2]), "r"(a[3]), "r"(b[0]), "r"(b[1]));
}
__device__ __forceinline__ void split_bf16(float v, unsigned short& h, unsigned short& l) {
    __nv_bfloat16 hb = __float2bfloat16(v);
    __nv_bfloat16 lb = __float2bfloat16(v - __bfloat162float(hb));
    h = __bfloat16_as_ushort(hb);
    l = __bfloat16_as_ushort(lb);
}

// ---------------- router ------------------------------------------------------
__global__ void router_kernel(const float* __restrict__ x,
                              const float* __restrict__ Wg) {
    const int n = blockIdx.x;
    const int t = threadIdx.x;
    float acc[NEXP];
#pragma unroll
    for (int e = 0; e < NEXP; e++) acc[e] = 0.f;
    const float* xr = x + (size_t)n * CDIM;
    for (int c = t; c < CDIM; c += 256) {
        float xv = xr[c];
        const float* wr = Wg + c * NEXP;
#pragma unroll
        for (int e = 0; e < NEXP; e++) acc[e] += xv * wr[e];
    }
#pragma unroll
    for (int off = 16; off; off >>= 1)
#pragma unroll
        for (int e = 0; e < NEXP; e++)
            acc[e] += __shfl_down_sync(0xffffffffu, acc[e], off);

    __shared__ float red[8][NEXP];
    if ((t & 31) == 0)
#pragma unroll
        for (int e = 0; e < NEXP; e++) red[t >> 5][e] = acc[e];
    __syncthreads();
    if (t == 0) {
        float l[NEXP];
#pragma unroll
        for (int e = 0; e < NEXP; e++) {
            float s = 0.f;
#pragma unroll
            for (int w = 0; w < 8; w++) s += red[w][e];
            l[e] = s;
        }
        float mx = l[0];
#pragma unroll
        for (int e = 1; e < NEXP; e++) mx = fmaxf(mx, l[e]);
        float p[NEXP];
#pragma unroll
        for (int e = 0; e < NEXP; e++) p[e] = expf(l[e] - mx);
        int i0 = 0;
#pragma unroll
        for (int e = 1; e < NEXP; e++) if (p[e] > p[i0]) i0 = e;
        int i1 = (i0 == 0) ? 1 : 0;
#pragma unroll
        for (int e = 0; e < NEXP; e++) if (e != i0 && p[e] > p[i1]) i1 = e;
        float s = p[i0] + p[i1];
        g_topi[2 * n]     = i0;
        g_topi[2 * n + 1] = i1;
        g_topw[2 * n]     = p[i0] / s;
        g_topw[2 * n + 1] = p[i1] / s;
    }
}

// ---------------- routing bookkeeping ----------------------------------------
__global__ void route_build_kernel() {
    __shared__ int cnt[NEXP], cur[NEXP];
    const int t = threadIdx.x;
    if (t < NEXP) cnt[t] = 0;
    __syncthreads();
    for (int i = t; i < NPAIR; i += 1024) atomicAdd(&cnt[g_topi[i]], 1);
    __syncthreads();
    if (t == 0) {
        int s = 0;
        for (int e = 0; e < NEXP; e++) {
            g_counts[e] = cnt[e];
            g_offs[e] = s; cur[e] = s; s += cnt[e];
        }
        g_offs[NEXP] = s;
    }
    __syncthreads();
    for (int i = t; i < NPAIR; i += 1024) {
        int e = g_topi[i];
        int pos = atomicAdd(&cur[e], 1);   // per-row math order-free -> deterministic
        g_rows[pos] = i >> 1;
        g_map[i]    = pos;
    }
}

// ---------------- streaming f32 -> bf16 hi/lo plane split --------------------
// sel: 0=W1, 1=W3, 2=W2, 3=x  (device-side symbol selection; device symbols
// must NOT be referenced from host code)
__global__ void fsplit_kernel(const float* __restrict__ src, int sel) {
    __nv_bfloat16* Oh;
    __nv_bfloat16* Ol;
    if (sel == 0)      { Oh = g_w1h; Ol = g_w1l; }
    else if (sel == 1) { Oh = g_w3h; Ol = g_w3l; }
    else if (sel == 2) { Oh = g_w2h; Ol = g_w2l; }
    else               { Oh = g_xh;  Ol = g_xl;  }
    size_t idx = (size_t)blockIdx.x * blockDim.x + threadIdx.x;
    const float4 v = ((const float4*)src)[idx];
    unsigned short h[4], l[4];
    split_bf16(v.x, h[0], l[0]); split_bf16(v.y, h[1], l[1]);
    split_bf16(v.z, h[2], l[2]); split_bf16(v.w, h[3], l[3]);
    uint2 hp, lp;
    hp.x = (unsigned)h[0] | ((unsigned)h[1] << 16);
    hp.y = (unsigned)h[2] | ((unsigned)h[3] << 16);
    lp.x = (unsigned)l[0] | ((unsigned)l[1] << 16);
    lp.y = (unsigned)l[2] | ((unsigned)l[3] << 16);
    ((uint2*)Oh)[idx] = hp;
    ((uint2*)Ol)[idx] = lp;
}

// ---------------- 3-stage cp.async split-bf16 tensor-core GEMM ---------------
#define TM 128
#define TN 128
#define TK 32
#define NSTG 3
#define ASTR 40
#define BSTR 136

struct SmemT {
    __nv_bfloat16 Ah[NSTG][TM][ASTR];
    __nv_bfloat16 Al[NSTG][TM][ASTR];
    __nv_bfloat16 Bh[NSTG][TK][BSTR];
    __nv_bfloat16 Bl[NSTG][TK][BSTR];
    int srow[TM];
};
#define AL_OFF (NSTG * TM * ASTR * 2)
#define BL_OFF (NSTG * TK * BSTR * 2)
#define SMEM_BYTES ((int)sizeof(SmemT))

// MODE 0: A=x planes (gather) B=W1 -> g_h1 fp32
// MODE 1: A=x planes (gather) B=W3 -> fused silu(h1)*h3 -> g_hh/g_hl
// MODE 2: A=hidden planes     B=W2 -> g_y fp32
template <int MODE>
__global__ __launch_bounds__(256) void gemm_tc() {
    constexpr int Kd = (MODE == 2) ? HDIM : CDIM;
    constexpr int Nd = (MODE == 2) ? CDIM : HDIM;
    constexpr int NS = Kd / TK;
    extern __shared__ char sm_raw[];
    SmemT& S = *reinterpret_cast<SmemT*>(sm_raw);

    const int e    = blockIdx.z;
    const int cnt  = g_counts[e];
    const int row0 = blockIdx.y * TM;
    if (row0 >= cnt) return;
    const int mrows    = min(TM, cnt - row0);
    const int slotbase = g_offs[e] + row0;
    const int nt0      = blockIdx.x * TN;

    const __nv_bfloat16* Ahg = (MODE < 2) ? g_xh : g_hh;
    const __nv_bfloat16* Alg = (MODE < 2) ? g_xl : g_hl;
    const __nv_bfloat16* Bh_g = (MODE == 0) ? g_w1h : (MODE == 1) ? g_w3h : g_w2h;
    const __nv_bfloat16* Bl_g = (MODE == 0) ? g_w1l : (MODE == 1) ? g_w3l : g_w2l;

    const int t = threadIdx.x;
    if (t < TM) {
        int m = min(t, mrows - 1);
        S.srow[t] = (MODE < 2) ? g_rows[slotbase + m] : (slotbase + m);
    }
    __syncthreads();

    const int lane = t & 31;
    const int warp = t >> 5;
    const int wm = (warp & 3) * 32;
    const int wn = (warp >> 2) * 64;

    // producer mapping: A: 2 threads/row, 2x16B per plane; B: 8 threads/krow
    const int ar = t >> 1;
    const int ac = (t & 1) * 16;
    const size_t myrow = (size_t)S.srow[ar];
    const __nv_bfloat16* pah = Ahg + myrow * Kd + ac;
    const __nv_bfloat16* pal = Alg + myrow * Kd + ac;
    const int bkr = t >> 3;
    const int bnc = (t & 7) * 16;
    const __nv_bfloat16* pbh = Bh_g + ((size_t)e * Kd + bkr) * Nd + nt0 + bnc;
    const __nv_bfloat16* pbl = Bl_g + ((size_t)e * Kd + bkr) * Nd + nt0 + bnc;

    float acc[2][8][4];
#pragma unroll
    for (int mi = 0; mi < 2; mi++)
#pragma unroll
        for (int ni = 0; ni < 8; ni++)
#pragma unroll
            for (int j = 0; j < 4; j++) acc[mi][ni][j] = 0.f;

    auto load_stage = [&](int s, int k0) {
        unsigned sa = sm_u32(&S.Ah[s][ar][ac]);
        cp16(sa,               pah + k0);
        cp16(sa + 16,          pah + k0 + 8);
        cp16(sa + AL_OFF,      pal + k0);
        cp16(sa + AL_OFF + 16, pal + k0 + 8);
        unsigned sb = sm_u32(&S.Bh[s][bkr][bnc]);
        const __nv_bfloat16* bh = pbh + (size_t)k0 * Nd;
        const __nv_bfloat16* bl = pbl + (size_t)k0 * Nd;
        cp16(sb,               bh);
        cp16(sb + 16,          bh + 8);
        cp16(sb + BL_OFF,      bl);
        cp16(sb + BL_OFF + 16, bl + 8);
        CP_COMMIT();
    };

    auto compute = [&](int s) {
#pragma unroll
        for (int kk = 0; kk < TK; kk += 16) {
            unsigned ah[2][4], al[2][4], bh[8][2], bl[8][2];
#pragma unroll
            for (int mh = 0; mh < 2; mh++) {
                unsigned a = sm_u32(&S.Ah[s][wm + mh * 16 + (lane & 15)][kk + (lane >> 4) * 8]);
                ldsm4(ah[mh], a);
                ldsm4(al[mh], a + AL_OFF);
            }
#pragma unroll
            for (int ng = 0; ng < 4; ng++) {
                unsigned a = sm_u32(&S.Bh[s][kk + (lane & 15)][wn + ng * 16 + (lane >> 4) * 8]);
                unsigned r[4], q[4];
                ldsm4t(r, a);
                ldsm4t(q, a + BL_OFF);
                bh[2 * ng][0] = r[0]; bh[2 * ng][1] = r[1];
                bh[2 * ng + 1][0] = r[2]; bh[2 * ng + 1][1] = r[3];
                bl[2 * ng][0] = q[0]; bl[2 * ng][1] = q[1];
                bl[2 * ng + 1][0] = q[2]; bl[2 * ng + 1][1] = q[3];
            }
#pragma unroll
            for (int mh = 0; mh < 2; mh++)
#pragma unroll
                for (int nf = 0; nf < 8; nf++) mma_bf16(acc[mh][nf], ah[mh], bh[nf]);
#pragma unroll
            for (int mh = 0; mh < 2; mh++)
#pragma unroll
                for (int nf = 0; nf < 8; nf++) mma_bf16(acc[mh][nf], al[mh], bh[nf]);
#pragma unroll
            for (int mh = 0; mh < 2; mh++)
#pragma unroll
                for (int nf = 0; nf < 8; nf++) mma_bf16(acc[mh][nf], ah[mh], bl[nf]);
        }
    };

    // prologue: 2 stages in flight
    load_stage(0, 0);
    load_stage(1, TK);

    int s = 0;
#pragma unroll 1
    for (int j = 0; j < NS; j++) {
        if (j == NS - 1) { CP_WAIT0(); } else { CP_WAIT1(); }   // stage j resident
        __syncthreads();          // all warps done with the slot being refilled
        if (j + 2 < NS) load_stage((s + 2 >= NSTG) ? s + 2 - NSTG : s + 2, (j + 2) * TK);
        compute(s);
        s = (s + 1 == NSTG) ? 0 : s + 1;
    }

    // ---------------- epilogue ----------------
    const int g = lane >> 2;
    const int q = lane & 3;
#pragma unroll
    for (int mh = 0; mh < 2; mh++)
#pragma unroll
        for (int nf = 0; nf < 8; nf++) {
            int r0 = wm + mh * 16 + g;
            int c  = nt0 + wn + nf * 8 + q * 2;
#pragma unroll
            for (int half = 0; half < 2; half++) {
                int r = r0 + half * 8;
                if (r >= mrows) continue;
                size_t orow = (size_t)(slotbase + r);
                float v0 = acc[mh][nf][2 * half];
                float v1 = acc[mh][nf][2 * half + 1];
                if (MODE == 0) {
                    float* p = g_h1 + orow * HDIM + c;
                    p[0] = v0; p[1] = v1;
                } else if (MODE == 1) {
                    const float* hp = g_h1 + orow * HDIM + c;
                    float a0 = hp[0], a1 = hp[1];
                    float w0 = a0 / (1.f + __expf(-a0)) * v0;
                    float w1 = a1 / (1.f + __expf(-a1)) * v1;
                    unsigned short h0, l0, h1, l1;
                    split_bf16(w0, h0, l0);
                    split_bf16(w1, h1, l1);
                    *(unsigned*)(g_hh + orow * HDIM + c) = (unsigned)h0 | ((unsigned)h1 << 16);
                    *(unsigned*)(g_hl + orow * HDIM + c) = (unsigned)l0 | ((unsigned)l1 << 16);
                } else {
                    float* p = g_y + orow * CDIM + c;
                    p[0] = v0; p[1] = v1;
                }
            }
        }
}

// ---------------- final gather-combine --------------------------------------
__global__ void combine_kernel(float* __restrict__ out) {
    int idx = blockIdx.x * blockDim.x + threadIdx.x;
    int n  = idx >> 8;
    int c4 = (idx & 255) << 2;
    int p0 = g_map[2 * n], p1 = g_map[2 * n + 1];
    float w0 = g_topw[2 * n], w1 = g_topw[2 * n + 1];
    float4 y0 = *(const float4*)(g_y + (size_t)p0 * CDIM + c4);
    float4 y1 = *(const float4*)(g_y + (size_t)p1 * CDIM + c4);
    float4 r;
    r.x = w0 * y0.x + w1 * y1.x;
    r.y = w0 * y0.y + w1 * y1.y;
    r.z = w0 * y0.z + w1 * y1.z;
    r.w = w0 * y0.w + w1 * y1.w;
    *(float4*)(out + (size_t)n * CDIM + c4) = r;
}

// ---------------- launch ------------------------------------------------------
extern "C" void kernel_launch(void* const* d_in, const int* in_sizes, int n_in,
                              void* d_out, int out_size) {
    const float* x  = (const float*)d_in[0];
    const float* Wg = (const float*)d_in[1];
    const float* W1 = (const float*)d_in[2];
    const float* W3 = (const float*)d_in[3];
    const float* W2 = (const float*)d_in[4];
    float* out = (float*)d_out;

    cudaFuncSetAttribute(gemm_tc<0>, cudaFuncAttributeMaxDynamicSharedMemorySize, SMEM_BYTES);
    cudaFuncSetAttribute(gemm_tc<1>, cudaFuncAttributeMaxDynamicSharedMemorySize, SMEM_BYTES);
    cudaFuncSetAttribute(gemm_tc<2>, cudaFuncAttributeMaxDynamicSharedMemorySize, SMEM_BYTES);

    const size_t WELEMS = (size_t)NEXP * CDIM * HDIM;   // 33.5M per tensor
    fsplit_kernel<<<(int)(WELEMS / 4 / 256), 256>>>(W1, 0);
    fsplit_kernel<<<(int)(WELEMS / 4 / 256), 256>>>(W3, 1);
    fsplit_kernel<<<(int)(WELEMS / 4 / 256), 256>>>(W2, 2);
    fsplit_kernel<<<(NTOK * CDIM / 4) / 256, 256>>>(x, 3);

    router_kernel<<<NTOK, 256>>>(x, Wg);
    route_build_kernel<<<1, 1024>>>();

    gemm_tc<0><<<dim3(HDIM / TN, NTOK / TM, NEXP), 256, SMEM_BYTES>>>();
    gemm_tc<1><<<dim3(HDIM / TN, NTOK / TM, NEXP), 256, SMEM_BYTES>>>();
    gemm_tc<2><<<dim3(CDIM / TN, NTOK / TM, NEXP), 256, SMEM_BYTES>>>();

    combine_kernel<<<(NTOK * (CDIM / 4)) / 256, 256>>>(out);
}

// round 7
// speedup vs baseline: 1.2288x; 1.0894x over previous
#include <cuda_runtime.h>
#include <cuda_bf16.h>
#include <math.h>

#define NTOK 4096
#define CDIM 1024
#define HDIM 4096
#define NEXP 8
#define NPAIR (NTOK * 2)

// ---------------- scratch (device globals) -----------------------------------
__device__ int   g_counts[NEXP];
__device__ int   g_offs[NEXP + 1];
__device__ int   g_topi[NPAIR];
__device__ float g_topw[NPAIR];
__device__ int   g_rows[NPAIR];
__device__ int   g_map[NPAIR];
__device__ __nv_bfloat16 g_xh[(size_t)NTOK * CDIM];
__device__ __nv_bfloat16 g_xl[(size_t)NTOK * CDIM];
__device__ float g_h1[(size_t)NPAIR * HDIM];
__device__ __nv_bfloat16 g_hh[(size_t)NPAIR * HDIM];
__device__ __nv_bfloat16 g_hl[(size_t)NPAIR * HDIM];
__device__ float g_y [(size_t)NPAIR * CDIM];
__device__ __nv_bfloat16 g_w1h[(size_t)NEXP * CDIM * HDIM];
__device__ __nv_bfloat16 g_w1l[(size_t)NEXP * CDIM * HDIM];
__device__ __nv_bfloat16 g_w3h[(size_t)NEXP * CDIM * HDIM];
__device__ __nv_bfloat16 g_w3l[(size_t)NEXP * CDIM * HDIM];
__device__ __nv_bfloat16 g_w2h[(size_t)NEXP * HDIM * CDIM];
__device__ __nv_bfloat16 g_w2l[(size_t)NEXP * HDIM * CDIM];

// ---------------- helpers -----------------------------------------------------
__device__ __forceinline__ unsigned sm_u32(const void* p) {
    return (unsigned)__cvta_generic_to_shared(p);
}
__device__ __forceinline__ void cp16(unsigned s, const void* g) {
    asm volatile("cp.async.cg.shared.global [%0], [%1], 16;\n" :: "r"(s), "l"(g));
}
#define CP_COMMIT() asm volatile("cp.async.commit_group;" ::: "memory")
#define CP_WAIT1()  asm volatile("cp.async.wait_group 1;" ::: "memory")
#define CP_WAIT0()  asm volatile("cp.async.wait_group 0;" ::: "memory")
__device__ __forceinline__ void ldsm4(unsigned* r, unsigned a) {
    asm volatile("ldmatrix.sync.aligned.m8n8.x4.shared.b16 {%0,%1,%2,%3}, [%4];"
                 : "=r"(r[0]), "=r"(r[1]), "=r"(r[2]), "=r"(r[3]) : "r"(a));
}
__device__ __forceinline__ void ldsm4t(unsigned* r, unsigned a) {
    asm volatile("ldmatrix.sync.aligned.m8n8.x4.trans.shared.b16 {%0,%1,%2,%3}, [%4];"
                 : "=r"(r[0]), "=r"(r[1]), "=r"(r[2]), "=r"(r[3]) : "r"(a));
}
__device__ __forceinline__ void mma_bf16(float* d, const unsigned* a, const unsigned* b) {
    asm volatile(
        "mma.sync.aligned.m16n8k16.row.col.f32.bf16.bf16.f32 "
        "{%0,%1,%2,%3}, {%4,%5,%6,%7}, {%8,%9}, {%0,%1,%2,%3};\n"
        : "+f"(d[0]), "+f"(d[1]), "+f"(d[2]), "+f"(d[3])
        : "r"(a[0]), "r"(a[1]), "r"(a[2]), "r"(a[3]), "r"(b[0]), "r"(b[1]));
}
__device__ __forceinline__ void split_bf16(float v, unsigned short& h, unsigned short& l) {
    __nv_bfloat16 hb = __float2bfloat16(v);
    __nv_bfloat16 lb = __float2bfloat16(v - __bfloat162float(hb));
    h = __bfloat16_as_ushort(hb);
    l = __bfloat16_as_ushort(lb);
}

// ---------------- router ------------------------------------------------------
__global__ void router_kernel(const float* __restrict__ x,
                              const float* __restrict__ Wg) {
    const int n = blockIdx.x;
    const int t = threadIdx.x;
    float acc[NEXP];
#pragma unroll
    for (int e = 0; e < NEXP; e++) acc[e] = 0.f;
    const float* xr = x + (size_t)n * CDIM;
    for (int c = t; c < CDIM; c += 256) {
        float xv = xr[c];
        const float* wr = Wg + c * NEXP;
#pragma unroll
        for (int e = 0; e < NEXP; e++) acc[e] += xv * wr[e];
    }
#pragma unroll
    for (int off = 16; off; off >>= 1)
#pragma unroll
        for (int e = 0; e < NEXP; e++)
            acc[e] += __shfl_down_sync(0xffffffffu, acc[e], off);

    __shared__ float red[8][NEXP];
    if ((t & 31) == 0)
#pragma unroll
        for (int e = 0; e < NEXP; e++) red[t >> 5][e] = acc[e];
    __syncthreads();
    if (t == 0) {
        float l[NEXP];
#pragma unroll
        for (int e = 0; e < NEXP; e++) {
            float s = 0.f;
#pragma unroll
            for (int w = 0; w < 8; w++) s += red[w][e];
            l[e] = s;
        }
        float mx = l[0];
#pragma unroll
        for (int e = 1; e < NEXP; e++) mx = fmaxf(mx, l[e]);
        float p[NEXP];
#pragma unroll
        for (int e = 0; e < NEXP; e++) p[e] = expf(l[e] - mx);
        int i0 = 0;
#pragma unroll
        for (int e = 1; e < NEXP; e++) if (p[e] > p[i0]) i0 = e;
        int i1 = (i0 == 0) ? 1 : 0;
#pragma unroll
        for (int e = 0; e < NEXP; e++) if (e != i0 && p[e] > p[i1]) i1 = e;
        float s = p[i0] + p[i1];
        g_topi[2 * n]     = i0;
        g_topi[2 * n + 1] = i1;
        g_topw[2 * n]     = p[i0] / s;
        g_topw[2 * n + 1] = p[i1] / s;
    }
}

// ---------------- routing bookkeeping ----------------------------------------
__global__ void route_build_kernel() {
    __shared__ int cnt[NEXP], cur[NEXP];
    const int t = threadIdx.x;
    if (t < NEXP) cnt[t] = 0;
    __syncthreads();
    for (int i = t; i < NPAIR; i += 1024) atomicAdd(&cnt[g_topi[i]], 1);
    __syncthreads();
    if (t == 0) {
        int s = 0;
        for (int e = 0; e < NEXP; e++) {
            g_counts[e] = cnt[e];
            g_offs[e] = s; cur[e] = s; s += cnt[e];
        }
        g_offs[NEXP] = s;
    }
    __syncthreads();
    for (int i = t; i < NPAIR; i += 1024) {
        int e = g_topi[i];
        int pos = atomicAdd(&cur[e], 1);   // per-row math order-free -> deterministic
        g_rows[pos] = i >> 1;
        g_map[i]    = pos;
    }
}

// ---------------- streaming f32 -> bf16 hi/lo plane split --------------------
__global__ void fsplit_kernel(const float* __restrict__ src, int sel) {
    __nv_bfloat16* Oh;
    __nv_bfloat16* Ol;
    if (sel == 0)      { Oh = g_w1h; Ol = g_w1l; }
    else if (sel == 1) { Oh = g_w3h; Ol = g_w3l; }
    else if (sel == 2) { Oh = g_w2h; Ol = g_w2l; }
    else               { Oh = g_xh;  Ol = g_xl;  }
    size_t idx = (size_t)blockIdx.x * blockDim.x + threadIdx.x;
    const float4 v = ((const float4*)src)[idx];
    unsigned short h[4], l[4];
    split_bf16(v.x, h[0], l[0]); split_bf16(v.y, h[1], l[1]);
    split_bf16(v.z, h[2], l[2]); split_bf16(v.w, h[3], l[3]);
    uint2 hp, lp;
    hp.x = (unsigned)h[0] | ((unsigned)h[1] << 16);
    hp.y = (unsigned)h[2] | ((unsigned)h[3] << 16);
    lp.x = (unsigned)l[0] | ((unsigned)l[1] << 16);
    lp.y = (unsigned)l[2] | ((unsigned)l[3] << 16);
    ((uint2*)Oh)[idx] = hp;
    ((uint2*)Ol)[idx] = lp;
}

// ---------------- 3-stage cp.async split-bf16 tensor-core GEMM ---------------
#define TM 128
#define TN 128
#define TK 32
#define NSTG 3
#define ASTR 40
#define BSTR 136

struct SmemT {
    __nv_bfloat16 Ah[NSTG][TM][ASTR];
    __nv_bfloat16 Al[NSTG][TM][ASTR];
    __nv_bfloat16 Bh[NSTG][TK][BSTR];
    __nv_bfloat16 Bl[NSTG][TK][BSTR];
    int srow[TM];
};
#define AL_OFF (NSTG * TM * ASTR * 2)
#define BL_OFF (NSTG * TK * BSTR * 2)
#define SMEM_BYTES ((int)sizeof(SmemT))

struct FragT {
    unsigned ah[2][4], al[2][4];
    unsigned bh[8][2], bl[8][2];
};

__device__ __forceinline__ void frag_load(FragT& f, SmemT& S, int s, int kk,
                                          int wm, int wn, int lane) {
#pragma unroll
    for (int mh = 0; mh < 2; mh++) {
        unsigned a = sm_u32(&S.Ah[s][wm + mh * 16 + (lane & 15)][kk + (lane >> 4) * 8]);
        ldsm4(f.ah[mh], a);
        ldsm4(f.al[mh], a + AL_OFF);
    }
#pragma unroll
    for (int ng = 0; ng < 4; ng++) {
        unsigned a = sm_u32(&S.Bh[s][kk + (lane & 15)][wn + ng * 16 + (lane >> 4) * 8]);
        unsigned r[4], q[4];
        ldsm4t(r, a);
        ldsm4t(q, a + BL_OFF);
        f.bh[2 * ng][0] = r[0]; f.bh[2 * ng][1] = r[1];
        f.bh[2 * ng + 1][0] = r[2]; f.bh[2 * ng + 1][1] = r[3];
        f.bl[2 * ng][0] = q[0]; f.bl[2 * ng][1] = q[1];
        f.bl[2 * ng + 1][0] = q[2]; f.bl[2 * ng + 1][1] = q[3];
    }
}

__device__ __forceinline__ void frag_mma(float acc[2][8][4], const FragT& f) {
#pragma unroll
    for (int mh = 0; mh < 2; mh++)
#pragma unroll
        for (int nf = 0; nf < 8; nf++) mma_bf16(acc[mh][nf], f.ah[mh], f.bh[nf]);
#pragma unroll
    for (int mh = 0; mh < 2; mh++)
#pragma unroll
        for (int nf = 0; nf < 8; nf++) mma_bf16(acc[mh][nf], f.al[mh], f.bh[nf]);
#pragma unroll
    for (int mh = 0; mh < 2; mh++)
#pragma unroll
        for (int nf = 0; nf < 8; nf++) mma_bf16(acc[mh][nf], f.ah[mh], f.bl[nf]);
}

// MODE 0: A=x planes (gather) B=W1 -> g_h1 fp32
// MODE 1: A=x planes (gather) B=W3 -> fused silu(h1)*h3 -> g_hh/g_hl
// MODE 2: A=hidden planes     B=W2 -> g_y fp32
template <int MODE>
__global__ __launch_bounds__(256) void gemm_tc() {
    constexpr int Kd = (MODE == 2) ? HDIM : CDIM;
    constexpr int Nd = (MODE == 2) ? CDIM : HDIM;
    constexpr int NS = Kd / TK;
    extern __shared__ char sm_raw[];
    SmemT& S = *reinterpret_cast<SmemT*>(sm_raw);

    const int e    = blockIdx.z;
    const int cnt  = g_counts[e];
    const int row0 = blockIdx.y * TM;
    if (row0 >= cnt) return;
    const int mrows    = min(TM, cnt - row0);
    const int slotbase = g_offs[e] + row0;
    const int nt0      = blockIdx.x * TN;

    const __nv_bfloat16* Ahg = (MODE < 2) ? g_xh : g_hh;
    const __nv_bfloat16* Alg = (MODE < 2) ? g_xl : g_hl;
    const __nv_bfloat16* Bh_g = (MODE == 0) ? g_w1h : (MODE == 1) ? g_w3h : g_w2h;
    const __nv_bfloat16* Bl_g = (MODE == 0) ? g_w1l : (MODE == 1) ? g_w3l : g_w2l;

    const int t = threadIdx.x;
    if (t < TM) {
        int m = min(t, mrows - 1);
        S.srow[t] = (MODE < 2) ? g_rows[slotbase + m] : (slotbase + m);
    }
    __syncthreads();

    const int lane = t & 31;
    const int warp = t >> 5;
    const int wm = (warp & 3) * 32;
    const int wn = (warp >> 2) * 64;

    // producer mapping: A: 2 threads/row, 2x16B per plane; B: 8 threads/krow
    const int ar = t >> 1;
    const int ac = (t & 1) * 16;
    const size_t myrow = (size_t)S.srow[ar];
    const __nv_bfloat16* pah = Ahg + myrow * Kd + ac;
    const __nv_bfloat16* pal = Alg + myrow * Kd + ac;
    const int bkr = t >> 3;
    const int bnc = (t & 7) * 16;
    const __nv_bfloat16* pbh = Bh_g + ((size_t)e * Kd + bkr) * Nd + nt0 + bnc;
    const __nv_bfloat16* pbl = Bl_g + ((size_t)e * Kd + bkr) * Nd + nt0 + bnc;

    float acc[2][8][4];
#pragma unroll
    for (int mi = 0; mi < 2; mi++)
#pragma unroll
        for (int ni = 0; ni < 8; ni++)
#pragma unroll
            for (int j = 0; j < 4; j++) acc[mi][ni][j] = 0.f;

    auto load_stage = [&](int s, int k0) {
        unsigned sa = sm_u32(&S.Ah[s][ar][ac]);
        cp16(sa,               pah + k0);
        cp16(sa + 16,          pah + k0 + 8);
        cp16(sa + AL_OFF,      pal + k0);
        cp16(sa + AL_OFF + 16, pal + k0 + 8);
        unsigned sb = sm_u32(&S.Bh[s][bkr][bnc]);
        const __nv_bfloat16* bh = pbh + (size_t)k0 * Nd;
        const __nv_bfloat16* bl = pbl + (size_t)k0 * Nd;
        cp16(sb,               bh);
        cp16(sb + 16,          bh + 8);
        cp16(sb + BL_OFF,      bl);
        cp16(sb + BL_OFF + 16, bl + 8);
        CP_COMMIT();
    };

    // prologue: stages 0,1 in flight; preload cur fragments from stage 0
    load_stage(0, 0);
    load_stage(1, TK);
    CP_WAIT1();              // stage 0 resident (this thread)
    __syncthreads();         // ...published block-wide
    FragT cur, nxt;
    frag_load(cur, S, 0, 0, wm, wn, lane);

#pragma unroll 1
    for (int j = 0; j < NS; j++) {
        const int s = j % NSTG;
        // LDSM batch issued a full MMA-burst ahead of its consumption:
        frag_load(nxt, S, s, 16, wm, wn, lane);
        frag_mma(acc, cur);                      // (stage j, kk=0)
        if (j + 2 < NS) {
            // refills slot (j-1)%3; its last reads were the nxt-load of iter
            // j-1, which precedes iter j-1's __syncthreads below.
            load_stage((j + 2) % NSTG, (j + 2) * TK);
            CP_WAIT1();      // this thread: groups <= j+1 complete
        } else {
            CP_WAIT0();
        }
        __syncthreads();     // publish stage j+1 block-wide (all threads waited)
        if (j + 1 < NS)
            frag_load(cur, S, (j + 1) % NSTG, 0, wm, wn, lane);  // now race-free
        frag_mma(acc, nxt);                      // (stage j, kk=16)
    }

    // ---------------- epilogue ----------------
    const int g = lane >> 2;
    const int q = lane & 3;
#pragma unroll
    for (int mh = 0; mh < 2; mh++)
#pragma unroll
        for (int nf = 0; nf < 8; nf++) {
            int r0 = wm + mh * 16 + g;
            int c  = nt0 + wn + nf * 8 + q * 2;
#pragma unroll
            for (int half = 0; half < 2; half++) {
                int r = r0 + half * 8;
                if (r >= mrows) continue;
                size_t orow = (size_t)(slotbase + r);
                float v0 = acc[mh][nf][2 * half];
                float v1 = acc[mh][nf][2 * half + 1];
                if (MODE == 0) {
                    float* p = g_h1 + orow * HDIM + c;
                    p[0] = v0; p[1] = v1;
                } else if (MODE == 1) {
                    const float* hp = g_h1 + orow * HDIM + c;
                    float a0 = hp[0], a1 = hp[1];
                    float w0 = a0 / (1.f + __expf(-a0)) * v0;
                    float w1 = a1 / (1.f + __expf(-a1)) * v1;
                    unsigned short h0, l0, h1, l1;
                    split_bf16(w0, h0, l0);
                    split_bf16(w1, h1, l1);
                    *(unsigned*)(g_hh + orow * HDIM + c) = (unsigned)h0 | ((unsigned)h1 << 16);
                    *(unsigned*)(g_hl + orow * HDIM + c) = (unsigned)l0 | ((unsigned)l1 << 16);
                } else {
                    float* p = g_y + orow * CDIM + c;
                    p[0] = v0; p[1] = v1;
                }
            }
        }
}

// ---------------- final gather-combine --------------------------------------
__global__ void combine_kernel(float* __restrict__ out) {
    int idx = blockIdx.x * blockDim.x + threadIdx.x;
    int n  = idx >> 8;
    int c4 = (idx & 255) << 2;
    int p0 = g_map[2 * n], p1 = g_map[2 * n + 1];
    float w0 = g_topw[2 * n], w1 = g_topw[2 * n + 1];
    float4 y0 = *(const float4*)(g_y + (size_t)p0 * CDIM + c4);
    float4 y1 = *(const float4*)(g_y + (size_t)p1 * CDIM + c4);
    float4 r;
    r.x = w0 * y0.x + w1 * y1.x;
    r.y = w0 * y0.y + w1 * y1.y;
    r.z = w0 * y0.z + w1 * y1.z;
    r.w = w0 * y0.w + w1 * y1.w;
    *(float4*)(out + (size_t)n * CDIM + c4) = r;
}

// ---------------- launch ------------------------------------------------------
extern "C" void kernel_launch(void* const* d_in, const int* in_sizes, int n_in,
                              void* d_out, int out_size) {
    const float* x  = (const float*)d_in[0];
    const float* Wg = (const float*)d_in[1];
    const float* W1 = (const float*)d_in[2];
    const float* W3 = (const float*)d_in[3];
    const float* W2 = (const float*)d_in[4];
    float* out = (float*)d_out;

    cudaFuncSetAttribute(gemm_tc<0>, cudaFuncAttributeMaxDynamicSharedMemorySize, SMEM_BYTES);
    cudaFuncSetAttribute(gemm_tc<1>, cudaFuncAttributeMaxDynamicSharedMemorySize, SMEM_BYTES);
    cudaFuncSetAttribute(gemm_tc<2>, cudaFuncAttributeMaxDynamicSharedMemorySize, SMEM_BYTES);

    const size_t WELEMS = (size_t)NEXP * CDIM * HDIM;
    fsplit_kernel<<<(int)(WELEMS / 4 / 256), 256>>>(W1, 0);
    fsplit_kernel<<<(int)(WELEMS / 4 / 256), 256>>>(W3, 1);
    fsplit_kernel<<<(int)(WELEMS / 4 / 256), 256>>>(W2, 2);
    fsplit_kernel<<<(NTOK * CDIM / 4) / 256, 256>>>(x, 3);

    router_kernel<<<NTOK, 256>>>(x, Wg);
    route_build_kernel<<<1, 1024>>>();

    gemm_tc<0><<<dim3(HDIM / TN, NTOK / TM, NEXP), 256, SMEM_BYTES>>>();
    gemm_tc<1><<<dim3(HDIM / TN, NTOK / TM, NEXP), 256, SMEM_BYTES>>>();
    gemm_tc<2><<<dim3(CDIM / TN, NTOK / TM, NEXP), 256, SMEM_BYTES>>>();

    combine_kernel<<<(NTOK * (CDIM / 4)) / 256, 256>>>(out);
}

// round 8
// speedup vs baseline: 1.3318x; 1.0838x over previous
#include <cuda_runtime.h>
#include <cuda_bf16.h>
#include <math.h>

#define NTOK 4096
#define CDIM 1024
#define HDIM 4096
#define NEXP 8
#define NPAIR (NTOK * 2)

// ---------------- scratch (device globals) -----------------------------------
__device__ int   g_counts[NEXP];
__device__ int   g_offs[NEXP + 1];
__device__ int   g_topi[NPAIR];
__device__ float g_topw[NPAIR];
__device__ int   g_rows[NPAIR];
__device__ int   g_map[NPAIR];
__device__ __nv_bfloat16 g_xh[(size_t)NTOK * CDIM];
__device__ __nv_bfloat16 g_xl[(size_t)NTOK * CDIM];
__device__ __nv_bfloat16 g_hh[(size_t)NPAIR * HDIM];
__device__ __nv_bfloat16 g_hl[(size_t)NPAIR * HDIM];
__device__ float g_y [(size_t)NPAIR * CDIM];
__device__ __nv_bfloat16 g_w1h[(size_t)NEXP * CDIM * HDIM];
__device__ __nv_bfloat16 g_w1l[(size_t)NEXP * CDIM * HDIM];
__device__ __nv_bfloat16 g_w3h[(size_t)NEXP * CDIM * HDIM];
__device__ __nv_bfloat16 g_w3l[(size_t)NEXP * CDIM * HDIM];
__device__ __nv_bfloat16 g_w2h[(size_t)NEXP * HDIM * CDIM];
__device__ __nv_bfloat16 g_w2l[(size_t)NEXP * HDIM * CDIM];

// ---------------- helpers -----------------------------------------------------
__device__ __forceinline__ unsigned sm_u32(const void* p) {
    return (unsigned)__cvta_generic_to_shared(p);
}
__device__ __forceinline__ void cp16(unsigned s, const void* g) {
    asm volatile("cp.async.cg.shared.global [%0], [%1], 16;\n" :: "r"(s), "l"(g));
}
#define CP_COMMIT() asm volatile("cp.async.commit_group;" ::: "memory")
#define CP_WAIT1()  asm volatile("cp.async.wait_group 1;" ::: "memory")
#define CP_WAIT0()  asm volatile("cp.async.wait_group 0;" ::: "memory")
__device__ __forceinline__ void ldsm4(unsigned* r, unsigned a) {
    asm volatile("ldmatrix.sync.aligned.m8n8.x4.shared.b16 {%0,%1,%2,%3}, [%4];"
                 : "=r"(r[0]), "=r"(r[1]), "=r"(r[2]), "=r"(r[3]) : "r"(a));
}
__device__ __forceinline__ void ldsm4t(unsigned* r, unsigned a) {
    asm volatile("ldmatrix.sync.aligned.m8n8.x4.trans.shared.b16 {%0,%1,%2,%3}, [%4];"
                 : "=r"(r[0]), "=r"(r[1]), "=r"(r[2]), "=r"(r[3]) : "r"(a));
}
__device__ __forceinline__ void mma_bf16(float* d, const unsigned* a, const unsigned* b) {
    asm volatile(
        "mma.sync.aligned.m16n8k16.row.col.f32.bf16.bf16.f32 "
        "{%0,%1,%2,%3}, {%4,%5,%6,%7}, {%8,%9}, {%0,%1,%2,%3};\n"
        : "+f"(d[0]), "+f"(d[1]), "+f"(d[2]), "+f"(d[3])
        : "r"(a[0]), "r"(a[1]), "r"(a[2]), "r"(a[3]), "r"(b[0]), "r"(b[1]));
}
__device__ __forceinline__ void split_bf16(float v, unsigned short& h, unsigned short& l) {
    __nv_bfloat16 hb = __float2bfloat16(v);
    __nv_bfloat16 lb = __float2bfloat16(v - __bfloat162float(hb));
    h = __bfloat16_as_ushort(hb);
    l = __bfloat16_as_ushort(lb);
}

// ---------------- router (fused with x hi/lo split) ---------------------------
__global__ void router_kernel(const float* __restrict__ x,
                              const float* __restrict__ Wg) {
    const int n = blockIdx.x;
    const int t = threadIdx.x;
    const int c0 = t * 4;
    const float4 v = *(const float4*)(x + (size_t)n * CDIM + c0);

    // fused x -> (xh, xl) store
    {
        unsigned short h[4], l[4];
        split_bf16(v.x, h[0], l[0]); split_bf16(v.y, h[1], l[1]);
        split_bf16(v.z, h[2], l[2]); split_bf16(v.w, h[3], l[3]);
        uint2 hp, lp;
        hp.x = (unsigned)h[0] | ((unsigned)h[1] << 16);
        hp.y = (unsigned)h[2] | ((unsigned)h[3] << 16);
        lp.x = (unsigned)l[0] | ((unsigned)l[1] << 16);
        lp.y = (unsigned)l[2] | ((unsigned)l[3] << 16);
        *(uint2*)(g_xh + (size_t)n * CDIM + c0) = hp;
        *(uint2*)(g_xl + (size_t)n * CDIM + c0) = lp;
    }

    float acc[NEXP];
#pragma unroll
    for (int e = 0; e < NEXP; e++) {
        acc[e] = v.x * Wg[(c0 + 0) * NEXP + e] + v.y * Wg[(c0 + 1) * NEXP + e]
               + v.z * Wg[(c0 + 2) * NEXP + e] + v.w * Wg[(c0 + 3) * NEXP + e];
    }
#pragma unroll
    for (int off = 16; off; off >>= 1)
#pragma unroll
        for (int e = 0; e < NEXP; e++)
            acc[e] += __shfl_down_sync(0xffffffffu, acc[e], off);

    __shared__ float red[8][NEXP];
    if ((t & 31) == 0)
#pragma unroll
        for (int e = 0; e < NEXP; e++) red[t >> 5][e] = acc[e];
    __syncthreads();
    if (t == 0) {
        float l[NEXP];
#pragma unroll
        for (int e = 0; e < NEXP; e++) {
            float s = 0.f;
#pragma unroll
            for (int w = 0; w < 8; w++) s += red[w][e];   // fixed order
            l[e] = s;
        }
        float mx = l[0];
#pragma unroll
        for (int e = 1; e < NEXP; e++) mx = fmaxf(mx, l[e]);
        float p[NEXP];
#pragma unroll
        for (int e = 0; e < NEXP; e++) p[e] = expf(l[e] - mx);
        int i0 = 0;
#pragma unroll
        for (int e = 1; e < NEXP; e++) if (p[e] > p[i0]) i0 = e;
        int i1 = (i0 == 0) ? 1 : 0;
#pragma unroll
        for (int e = 0; e < NEXP; e++) if (e != i0 && p[e] > p[i1]) i1 = e;
        float s = p[i0] + p[i1];
        g_topi[2 * n]     = i0;
        g_topi[2 * n + 1] = i1;
        g_topw[2 * n]     = p[i0] / s;
        g_topw[2 * n + 1] = p[i1] / s;
    }
}

// ---------------- routing bookkeeping ----------------------------------------
__global__ void route_build_kernel() {
    __shared__ int cnt[NEXP], cur[NEXP];
    const int t = threadIdx.x;
    if (t < NEXP) cnt[t] = 0;
    __syncthreads();
    for (int i = t; i < NPAIR; i += 1024) atomicAdd(&cnt[g_topi[i]], 1);
    __syncthreads();
    if (t == 0) {
        int s = 0;
        for (int e = 0; e < NEXP; e++) {
            g_counts[e] = cnt[e];
            g_offs[e] = s; cur[e] = s; s += cnt[e];
        }
        g_offs[NEXP] = s;
    }
    __syncthreads();
    for (int i = t; i < NPAIR; i += 1024) {
        int e = g_topi[i];
        int pos = atomicAdd(&cur[e], 1);   // per-row math order-free -> deterministic
        g_rows[pos] = i >> 1;
        g_map[i]    = pos;
    }
}

// ---------------- weight hi/lo splits -----------------------------------------
// one launch for W1 + W3 (blockIdx.y selects)
__global__ void fsplit_w13_kernel(const float* __restrict__ W1,
                                  const float* __restrict__ W3) {
    const int which = blockIdx.y;
    const float* src = which ? W3 : W1;
    __nv_bfloat16* Oh = which ? g_w3h : g_w1h;
    __nv_bfloat16* Ol = which ? g_w3l : g_w1l;
    size_t idx = (size_t)blockIdx.x * blockDim.x + threadIdx.x;
    const float4 v = ((const float4*)src)[idx];
    unsigned short h[4], l[4];
    split_bf16(v.x, h[0], l[0]); split_bf16(v.y, h[1], l[1]);
    split_bf16(v.z, h[2], l[2]); split_bf16(v.w, h[3], l[3]);
    uint2 hp, lp;
    hp.x = (unsigned)h[0] | ((unsigned)h[1] << 16);
    hp.y = (unsigned)h[2] | ((unsigned)h[3] << 16);
    lp.x = (unsigned)l[0] | ((unsigned)l[1] << 16);
    lp.y = (unsigned)l[2] | ((unsigned)l[3] << 16);
    ((uint2*)Oh)[idx] = hp;
    ((uint2*)Ol)[idx] = lp;
}

__global__ void fsplit_w2_kernel(const float* __restrict__ W2) {
    size_t idx = (size_t)blockIdx.x * blockDim.x + threadIdx.x;
    const float4 v = ((const float4*)W2)[idx];
    unsigned short h[4], l[4];
    split_bf16(v.x, h[0], l[0]); split_bf16(v.y, h[1], l[1]);
    split_bf16(v.z, h[2], l[2]); split_bf16(v.w, h[3], l[3]);
    uint2 hp, lp;
    hp.x = (unsigned)h[0] | ((unsigned)h[1] << 16);
    hp.y = (unsigned)h[2] | ((unsigned)h[3] << 16);
    lp.x = (unsigned)l[0] | ((unsigned)l[1] << 16);
    lp.y = (unsigned)l[2] | ((unsigned)l[3] << 16);
    ((uint2*)g_w2h)[idx] = hp;
    ((uint2*)g_w2l)[idx] = lp;
}

// ---------------- shared GEMM params ------------------------------------------
#define TM 128
#define TK 32
#define NSTG 3
#define ASTR 40

// ======================= fused W1+W3 GEMM (MODE 0+1) ==========================
// CTA tile: M=128, N=64 per weight tensor (both at same n-range).
// Epilogue: h = silu(d1) * d3 -> bf16 hi/lo planes, no fp32 round trip.
#define BSTRF 72

struct SmemF {
    __nv_bfloat16 Ah[NSTG][TM][ASTR];
    __nv_bfloat16 Al[NSTG][TM][ASTR];
    __nv_bfloat16 B1h[NSTG][TK][BSTRF];
    __nv_bfloat16 B1l[NSTG][TK][BSTRF];
    __nv_bfloat16 B3h[NSTG][TK][BSTRF];
    __nv_bfloat16 B3l[NSTG][TK][BSTRF];
    int srow[TM];
};
#define AL_OFF  (NSTG * TM * ASTR * 2)
#define BFL_OFF (NSTG * TK * BSTRF * 2)
#define SMEMF_BYTES ((int)sizeof(SmemF))

struct FragF {
    unsigned ah[2][4], al[2][4];
    unsigned b1h[4][2], b1l[4][2];
    unsigned b3h[4][2], b3l[4][2];
};

__device__ __forceinline__ void frag_load_f(FragF& f, SmemF& S, int s, int kk,
                                            int wm, int wn, int lane) {
#pragma unroll
    for (int mh = 0; mh < 2; mh++) {
        unsigned a = sm_u32(&S.Ah[s][wm + mh * 16 + (lane & 15)][kk + (lane >> 4) * 8]);
        ldsm4(f.ah[mh], a);
        ldsm4(f.al[mh], a + AL_OFF);
    }
#pragma unroll
    for (int ng = 0; ng < 2; ng++) {
        unsigned a1 = sm_u32(&S.B1h[s][kk + (lane & 15)][wn + ng * 16 + (lane >> 4) * 8]);
        unsigned r[4], q[4];
        ldsm4t(r, a1);
        ldsm4t(q, a1 + BFL_OFF);
        f.b1h[2 * ng][0] = r[0]; f.b1h[2 * ng][1] = r[1];
        f.b1h[2 * ng + 1][0] = r[2]; f.b1h[2 * ng + 1][1] = r[3];
        f.b1l[2 * ng][0] = q[0]; f.b1l[2 * ng][1] = q[1];
        f.b1l[2 * ng + 1][0] = q[2]; f.b1l[2 * ng + 1][1] = q[3];
        unsigned a3 = sm_u32(&S.B3h[s][kk + (lane & 15)][wn + ng * 16 + (lane >> 4) * 8]);
        ldsm4t(r, a3);
        ldsm4t(q, a3 + BFL_OFF);
        f.b3h[2 * ng][0] = r[0]; f.b3h[2 * ng][1] = r[1];
        f.b3h[2 * ng + 1][0] = r[2]; f.b3h[2 * ng + 1][1] = r[3];
        f.b3l[2 * ng][0] = q[0]; f.b3l[2 * ng][1] = q[1];
        f.b3l[2 * ng + 1][0] = q[2]; f.b3l[2 * ng + 1][1] = q[3];
    }
}

__device__ __forceinline__ void frag_mma_f(float acc1[2][4][4], float acc3[2][4][4],
                                           const FragF& f) {
#pragma unroll
    for (int mh = 0; mh < 2; mh++)
#pragma unroll
        for (int nf = 0; nf < 4; nf++) mma_bf16(acc1[mh][nf], f.ah[mh], f.b1h[nf]);
#pragma unroll
    for (int mh = 0; mh < 2; mh++)
#pragma unroll
        for (int nf = 0; nf < 4; nf++) mma_bf16(acc3[mh][nf], f.ah[mh], f.b3h[nf]);
#pragma unroll
    for (int mh = 0; mh < 2; mh++)
#pragma unroll
        for (int nf = 0; nf < 4; nf++) mma_bf16(acc1[mh][nf], f.al[mh], f.b1h[nf]);
#pragma unroll
    for (int mh = 0; mh < 2; mh++)
#pragma unroll
        for (int nf = 0; nf < 4; nf++) mma_bf16(acc3[mh][nf], f.al[mh], f.b3h[nf]);
#pragma unroll
    for (int mh = 0; mh < 2; mh++)
#pragma unroll
        for (int nf = 0; nf < 4; nf++) mma_bf16(acc1[mh][nf], f.ah[mh], f.b1l[nf]);
#pragma unroll
    for (int mh = 0; mh < 2; mh++)
#pragma unroll
        for (int nf = 0; nf < 4; nf++) mma_bf16(acc3[mh][nf], f.ah[mh], f.b3l[nf]);
}

__global__ __launch_bounds__(256) void gemm_fused13() {
    constexpr int Kd = CDIM;
    constexpr int Nd = HDIM;
    constexpr int NS = Kd / TK;
    extern __shared__ char sm_raw[];
    SmemF& S = *reinterpret_cast<SmemF*>(sm_raw);

    const int e    = blockIdx.z;
    const int cnt  = g_counts[e];
    const int row0 = blockIdx.y * TM;
    if (row0 >= cnt) return;
    const int mrows    = min(TM, cnt - row0);
    const int slotbase = g_offs[e] + row0;
    const int nt0      = blockIdx.x * 64;

    const int t = threadIdx.x;
    if (t < TM) {
        int m = min(t, mrows - 1);
        S.srow[t] = g_rows[slotbase + m];
    }
    __syncthreads();

    const int lane = t & 31;
    const int warp = t >> 5;
    const int wm = (warp & 3) * 32;
    const int wn = (warp >> 2) * 32;

    // producers: A: 2 threads/row x 32B (two cp16) per plane; B: 1 cp16/plane/tensor
    const int ar = t >> 1;
    const int ac = (t & 1) * 16;
    const size_t myrow = (size_t)S.srow[ar];
    const __nv_bfloat16* pah = g_xh + myrow * Kd + ac;
    const __nv_bfloat16* pal = g_xl + myrow * Kd + ac;
    const int bkr = t >> 3;          // 0..31
    const int bnc = (t & 7) * 8;     // 0..56
    const size_t boff = ((size_t)e * Kd + bkr) * Nd + nt0 + bnc;
    const __nv_bfloat16* pb1h = g_w1h + boff;
    const __nv_bfloat16* pb1l = g_w1l + boff;
    const __nv_bfloat16* pb3h = g_w3h + boff;
    const __nv_bfloat16* pb3l = g_w3l + boff;

    float acc1[2][4][4], acc3[2][4][4];
#pragma unroll
    for (int mi = 0; mi < 2; mi++)
#pragma unroll
        for (int ni = 0; ni < 4; ni++)
#pragma unroll
            for (int j = 0; j < 4; j++) { acc1[mi][ni][j] = 0.f; acc3[mi][ni][j] = 0.f; }

    auto load_stage = [&](int s, int k0) {
        unsigned sa = sm_u32(&S.Ah[s][ar][ac]);
        cp16(sa,               pah + k0);
        cp16(sa + 16,          pah + k0 + 8);
        cp16(sa + AL_OFF,      pal + k0);
        cp16(sa + AL_OFF + 16, pal + k0 + 8);
        unsigned sb1 = sm_u32(&S.B1h[s][bkr][bnc]);
        unsigned sb3 = sm_u32(&S.B3h[s][bkr][bnc]);
        const size_t ko = (size_t)k0 * Nd;
        cp16(sb1,            pb1h + ko);
        cp16(sb1 + BFL_OFF,  pb1l + ko);
        cp16(sb3,            pb3h + ko);
        cp16(sb3 + BFL_OFF,  pb3l + ko);
        CP_COMMIT();
    };

    load_stage(0, 0);
    load_stage(1, TK);
    CP_WAIT1();
    __syncthreads();
    FragF cur, nxt;
    frag_load_f(cur, S, 0, 0, wm, wn, lane);

#pragma unroll 1
    for (int j = 0; j < NS; j++) {
        const int s = j % NSTG;
        frag_load_f(nxt, S, s, 16, wm, wn, lane);
        frag_mma_f(acc1, acc3, cur);                    // (stage j, kk=0)
        if (j + 2 < NS) {
            load_stage((j + 2) % NSTG, (j + 2) * TK);
            CP_WAIT1();
        } else {
            CP_WAIT0();
        }
        __syncthreads();                                // publish stage j+1
        if (j + 1 < NS)
            frag_load_f(cur, S, (j + 1) % NSTG, 0, wm, wn, lane);
        frag_mma_f(acc1, acc3, nxt);                    // (stage j, kk=16)
    }

    // epilogue: h = silu(d1) * d3 -> hi/lo bf16 planes (no fp32 round trip)
    const int g = lane >> 2;
    const int q = lane & 3;
#pragma unroll
    for (int mh = 0; mh < 2; mh++)
#pragma unroll
        for (int nf = 0; nf < 4; nf++) {
            int r0 = wm + mh * 16 + g;
            int c  = nt0 + wn + nf * 8 + q * 2;
#pragma unroll
            for (int half = 0; half < 2; half++) {
                int r = r0 + half * 8;
                if (r >= mrows) continue;
                size_t orow = (size_t)(slotbase + r);
                float d10 = acc1[mh][nf][2 * half], d11 = acc1[mh][nf][2 * half + 1];
                float d30 = acc3[mh][nf][2 * half], d31 = acc3[mh][nf][2 * half + 1];
                float w0 = d10 / (1.f + __expf(-d10)) * d30;
                float w1 = d11 / (1.f + __expf(-d11)) * d31;
                unsigned short h0, l0, h1, l1;
                split_bf16(w0, h0, l0);
                split_bf16(w1, h1, l1);
                *(unsigned*)(g_hh + orow * HDIM + c) = (unsigned)h0 | ((unsigned)h1 << 16);
                *(unsigned*)(g_hl + orow * HDIM + c) = (unsigned)l0 | ((unsigned)l1 << 16);
            }
        }
}

// ======================= W2 GEMM (hidden -> y) ================================
#define TN2 128
#define BSTR2 136

struct Smem2 {
    __nv_bfloat16 Ah[NSTG][TM][ASTR];
    __nv_bfloat16 Al[NSTG][TM][ASTR];
    __nv_bfloat16 Bh[NSTG][TK][BSTR2];
    __nv_bfloat16 Bl[NSTG][TK][BSTR2];
    int srow[TM];
};
#define B2L_OFF (NSTG * TK * BSTR2 * 2)
#define SMEM2_BYTES ((int)sizeof(Smem2))

struct Frag2 {
    unsigned ah[2][4], al[2][4];
    unsigned bh[8][2], bl[8][2];
};

__device__ __forceinline__ void frag_load_2(Frag2& f, Smem2& S, int s, int kk,
                                            int wm, int wn, int lane) {
#pragma unroll
    for (int mh = 0; mh < 2; mh++) {
        unsigned a = sm_u32(&S.Ah[s][wm + mh * 16 + (lane & 15)][kk + (lane >> 4) * 8]);
        ldsm4(f.ah[mh], a);
        ldsm4(f.al[mh], a + AL_OFF);
    }
#pragma unroll
    for (int ng = 0; ng < 4; ng++) {
        unsigned a = sm_u32(&S.Bh[s][kk + (lane & 15)][wn + ng * 16 + (lane >> 4) * 8]);
        unsigned r[4], q[4];
        ldsm4t(r, a);
        ldsm4t(q, a + B2L_OFF);
        f.bh[2 * ng][0] = r[0]; f.bh[2 * ng][1] = r[1];
        f.bh[2 * ng + 1][0] = r[2]; f.bh[2 * ng + 1][1] = r[3];
        f.bl[2 * ng][0] = q[0]; f.bl[2 * ng][1] = q[1];
        f.bl[2 * ng + 1][0] = q[2]; f.bl[2 * ng + 1][1] = q[3];
    }
}

__device__ __forceinline__ void frag_mma_2(float acc[2][8][4], const Frag2& f) {
#pragma unroll
    for (int mh = 0; mh < 2; mh++)
#pragma unroll
        for (int nf = 0; nf < 8; nf++) mma_bf16(acc[mh][nf], f.ah[mh], f.bh[nf]);
#pragma unroll
    for (int mh = 0; mh < 2; mh++)
#pragma unroll
        for (int nf = 0; nf < 8; nf++) mma_bf16(acc[mh][nf], f.al[mh], f.bh[nf]);
#pragma unroll
    for (int mh = 0; mh < 2; mh++)
#pragma unroll
        for (int nf = 0; nf < 8; nf++) mma_bf16(acc[mh][nf], f.ah[mh], f.bl[nf]);
}

__global__ __launch_bounds__(256) void gemm_w2() {
    constexpr int Kd = HDIM;
    constexpr int Nd = CDIM;
    constexpr int NS = Kd / TK;
    extern __shared__ char sm_raw[];
    Smem2& S = *reinterpret_cast<Smem2*>(sm_raw);

    const int e    = blockIdx.z;
    const int cnt  = g_counts[e];
    const int row0 = blockIdx.y * TM;
    if (row0 >= cnt) return;
    const int mrows    = min(TM, cnt - row0);
    const int slotbase = g_offs[e] + row0;
    const int nt0      = blockIdx.x * TN2;

    const int t = threadIdx.x;
    if (t < TM) S.srow[t] = slotbase + min(t, mrows - 1);
    __syncthreads();

    const int lane = t & 31;
    const int warp = t >> 5;
    const int wm = (warp & 3) * 32;
    const int wn = (warp >> 2) * 64;

    const int ar = t >> 1;
    const int ac = (t & 1) * 16;
    const size_t myrow = (size_t)S.srow[ar];
    const __nv_bfloat16* pah = g_hh + myrow * Kd + ac;
    const __nv_bfloat16* pal = g_hl + myrow * Kd + ac;
    const int bkr = t >> 3;
    const int bnc = (t & 7) * 16;
    const __nv_bfloat16* pbh = g_w2h + ((size_t)e * Kd + bkr) * Nd + nt0 + bnc;
    const __nv_bfloat16* pbl = g_w2l + ((size_t)e * Kd + bkr) * Nd + nt0 + bnc;

    float acc[2][8][4];
#pragma unroll
    for (int mi = 0; mi < 2; mi++)
#pragma unroll
        for (int ni = 0; ni < 8; ni++)
#pragma unroll
            for (int j = 0; j < 4; j++) acc[mi][ni][j] = 0.f;

    auto load_stage = [&](int s, int k0) {
        unsigned sa = sm_u32(&S.Ah[s][ar][ac]);
        cp16(sa,               pah + k0);
        cp16(sa + 16,          pah + k0 + 8);
        cp16(sa + AL_OFF,      pal + k0);
        cp16(sa + AL_OFF + 16, pal + k0 + 8);
        unsigned sb = sm_u32(&S.Bh[s][bkr][bnc]);
        const __nv_bfloat16* bh = pbh + (size_t)k0 * Nd;
        const __nv_bfloat16* bl = pbl + (size_t)k0 * Nd;
        cp16(sb,               bh);
        cp16(sb + 16,          bh + 8);
        cp16(sb + B2L_OFF,     bl);
        cp16(sb + B2L_OFF + 16, bl + 8);
        CP_COMMIT();
    };

    load_stage(0, 0);
    load_stage(1, TK);
    CP_WAIT1();
    __syncthreads();
    Frag2 cur, nxt;
    frag_load_2(cur, S, 0, 0, wm, wn, lane);

#pragma unroll 1
    for (int j = 0; j < NS; j++) {
        const int s = j % NSTG;
        frag_load_2(nxt, S, s, 16, wm, wn, lane);
        frag_mma_2(acc, cur);
        if (j + 2 < NS) {
            load_stage((j + 2) % NSTG, (j + 2) * TK);
            CP_WAIT1();
        } else {
            CP_WAIT0();
        }
        __syncthreads();
        if (j + 1 < NS)
            frag_load_2(cur, S, (j + 1) % NSTG, 0, wm, wn, lane);
        frag_mma_2(acc, nxt);
    }

    const int g = lane >> 2;
    const int q = lane & 3;
#pragma unroll
    for (int mh = 0; mh < 2; mh++)
#pragma unroll
        for (int nf = 0; nf < 8; nf++) {
            int r0 = wm + mh * 16 + g;
            int c  = nt0 + wn + nf * 8 + q * 2;
#pragma unroll
            for (int half = 0; half < 2; half++) {
                int r = r0 + half * 8;
                if (r >= mrows) continue;
                size_t orow = (size_t)(slotbase + r);
                float* p = g_y + orow * CDIM + c;
                p[0] = acc[mh][nf][2 * half];
                p[1] = acc[mh][nf][2 * half + 1];
            }
        }
}

// ---------------- final gather-combine --------------------------------------
__global__ void combine_kernel(float* __restrict__ out) {
    int idx = blockIdx.x * blockDim.x + threadIdx.x;
    int n  = idx >> 8;
    int c4 = (idx & 255) << 2;
    int p0 = g_map[2 * n], p1 = g_map[2 * n + 1];
    float w0 = g_topw[2 * n], w1 = g_topw[2 * n + 1];
    float4 y0 = *(const float4*)(g_y + (size_t)p0 * CDIM + c4);
    float4 y1 = *(const float4*)(g_y + (size_t)p1 * CDIM + c4);
    float4 r;
    r.x = w0 * y0.x + w1 * y1.x;
    r.y = w0 * y0.y + w1 * y1.y;
    r.z = w0 * y0.z + w1 * y1.z;
    r.w = w0 * y0.w + w1 * y1.w;
    *(float4*)(out + (size_t)n * CDIM + c4) = r;
}

// ---------------- launch ------------------------------------------------------
extern "C" void kernel_launch(void* const* d_in, const int* in_sizes, int n_in,
                              void* d_out, int out_size) {
    const float* x  = (const float*)d_in[0];
    const float* Wg = (const float*)d_in[1];
    const float* W1 = (const float*)d_in[2];
    const float* W3 = (const float*)d_in[3];
    const float* W2 = (const float*)d_in[4];
    float* out = (float*)d_out;

    cudaFuncSetAttribute(gemm_fused13, cudaFuncAttributeMaxDynamicSharedMemorySize, SMEMF_BYTES);
    cudaFuncSetAttribute(gemm_w2, cudaFuncAttributeMaxDynamicSharedMemorySize, SMEM2_BYTES);

    const size_t WELEMS = (size_t)NEXP * CDIM * HDIM;

    // launch index 3 = gemm_fused13 (ncu captures index 3)
    fsplit_w13_kernel<<<dim3((unsigned)(WELEMS / 4 / 256), 2), 256>>>(W1, W3);  // 0
    router_kernel<<<NTOK, 256>>>(x, Wg);                                        // 1
    route_build_kernel<<<1, 1024>>>();                                          // 2
    gemm_fused13<<<dim3(HDIM / 64, NTOK / TM, NEXP), 256, SMEMF_BYTES>>>();     // 3
    fsplit_w2_kernel<<<(unsigned)(WELEMS / 4 / 256), 256>>>(W2);                // 4
    gemm_w2<<<dim3(CDIM / TN2, NTOK / TM, NEXP), 256, SMEM2_BYTES>>>();         // 5
    combine_kernel<<<(NTOK * (CDIM / 4)) / 256, 256>>>(out);                    // 6
}

// round 9
// speedup vs baseline: 1.6302x; 1.2241x over previous
#include <cuda_runtime.h>
#include <cuda_fp16.h>
#include <math.h>

#define NTOK 4096
#define CDIM 1024
#define HDIM 4096
#define NEXP 8
#define NPAIR (NTOK * 2)

// ---------------- scratch (device globals) -----------------------------------
__device__ int   g_counts[NEXP];
__device__ int   g_offs[NEXP + 1];
__device__ int   g_topi[NPAIR];
__device__ float g_topw[NPAIR];
__device__ int   g_rows[NPAIR];
__device__ int   g_map[NPAIR];
__device__ __half g_xh[(size_t)NTOK * CDIM];     // x hi plane (fp16)
__device__ __half g_xl[(size_t)NTOK * CDIM];     // x lo plane
__device__ __half g_hh[(size_t)NPAIR * HDIM];    // hidden hi
__device__ __half g_hl[(size_t)NPAIR * HDIM];    // hidden lo
__device__ float g_y [(size_t)NPAIR * CDIM];
__device__ __half g_w1f[(size_t)NEXP * CDIM * HDIM];  // weights: single fp16 plane
__device__ __half g_w3f[(size_t)NEXP * CDIM * HDIM];
__device__ __half g_w2f[(size_t)NEXP * HDIM * CDIM];

// ---------------- helpers -----------------------------------------------------
__device__ __forceinline__ unsigned sm_u32(const void* p) {
    return (unsigned)__cvta_generic_to_shared(p);
}
__device__ __forceinline__ void cp16(unsigned s, const void* g) {
    asm volatile("cp.async.cg.shared.global [%0], [%1], 16;\n" :: "r"(s), "l"(g));
}
#define CP_COMMIT() asm volatile("cp.async.commit_group;" ::: "memory")
#define CP_WAIT1()  asm volatile("cp.async.wait_group 1;" ::: "memory")
#define CP_WAIT0()  asm volatile("cp.async.wait_group 0;" ::: "memory")
__device__ __forceinline__ void ldsm4(unsigned* r, unsigned a) {
    asm volatile("ldmatrix.sync.aligned.m8n8.x4.shared.b16 {%0,%1,%2,%3}, [%4];"
                 : "=r"(r[0]), "=r"(r[1]), "=r"(r[2]), "=r"(r[3]) : "r"(a));
}
__device__ __forceinline__ void ldsm4t(unsigned* r, unsigned a) {
    asm volatile("ldmatrix.sync.aligned.m8n8.x4.trans.shared.b16 {%0,%1,%2,%3}, [%4];"
                 : "=r"(r[0]), "=r"(r[1]), "=r"(r[2]), "=r"(r[3]) : "r"(a));
}
__device__ __forceinline__ void mma_f16(float* d, const unsigned* a, const unsigned* b) {
    asm volatile(
        "mma.sync.aligned.m16n8k16.row.col.f32.f16.f16.f32 "
        "{%0,%1,%2,%3}, {%4,%5,%6,%7}, {%8,%9}, {%0,%1,%2,%3};\n"
        : "+f"(d[0]), "+f"(d[1]), "+f"(d[2]), "+f"(d[3])
        : "r"(a[0]), "r"(a[1]), "r"(a[2]), "r"(a[3]), "r"(b[0]), "r"(b[1]));
}
__device__ __forceinline__ void split_f16(float v, unsigned short& h, unsigned short& l) {
    __half hb = __float2half_rn(v);
    __half lb = __float2half_rn(v - __half2float(hb));
    h = __half_as_ushort(hb);
    l = __half_as_ushort(lb);
}

// ---------------- router (fused with x hi/lo fp16 split) ----------------------
__global__ void router_kernel(const float* __restrict__ x,
                              const float* __restrict__ Wg) {
    const int n = blockIdx.x;
    const int t = threadIdx.x;
    const int c0 = t * 4;
    const float4 v = *(const float4*)(x + (size_t)n * CDIM + c0);

    {
        unsigned short h[4], l[4];
        split_f16(v.x, h[0], l[0]); split_f16(v.y, h[1], l[1]);
        split_f16(v.z, h[2], l[2]); split_f16(v.w, h[3], l[3]);
        uint2 hp, lp;
        hp.x = (unsigned)h[0] | ((unsigned)h[1] << 16);
        hp.y = (unsigned)h[2] | ((unsigned)h[3] << 16);
        lp.x = (unsigned)l[0] | ((unsigned)l[1] << 16);
        lp.y = (unsigned)l[2] | ((unsigned)l[3] << 16);
        *(uint2*)(g_xh + (size_t)n * CDIM + c0) = hp;
        *(uint2*)(g_xl + (size_t)n * CDIM + c0) = lp;
    }

    float acc[NEXP];
#pragma unroll
    for (int e = 0; e < NEXP; e++) {
        acc[e] = v.x * Wg[(c0 + 0) * NEXP + e] + v.y * Wg[(c0 + 1) * NEXP + e]
               + v.z * Wg[(c0 + 2) * NEXP + e] + v.w * Wg[(c0 + 3) * NEXP + e];
    }
#pragma unroll
    for (int off = 16; off; off >>= 1)
#pragma unroll
        for (int e = 0; e < NEXP; e++)
            acc[e] += __shfl_down_sync(0xffffffffu, acc[e], off);

    __shared__ float red[8][NEXP];
    if ((t & 31) == 0)
#pragma unroll
        for (int e = 0; e < NEXP; e++) red[t >> 5][e] = acc[e];
    __syncthreads();
    if (t == 0) {
        float l[NEXP];
#pragma unroll
        for (int e = 0; e < NEXP; e++) {
            float s = 0.f;
#pragma unroll
            for (int w = 0; w < 8; w++) s += red[w][e];   // fixed order
            l[e] = s;
        }
        float mx = l[0];
#pragma unroll
        for (int e = 1; e < NEXP; e++) mx = fmaxf(mx, l[e]);
        float p[NEXP];
#pragma unroll
        for (int e = 0; e < NEXP; e++) p[e] = expf(l[e] - mx);
        int i0 = 0;
#pragma unroll
        for (int e = 1; e < NEXP; e++) if (p[e] > p[i0]) i0 = e;
        int i1 = (i0 == 0) ? 1 : 0;
#pragma unroll
        for (int e = 0; e < NEXP; e++) if (e != i0 && p[e] > p[i1]) i1 = e;
        float s = p[i0] + p[i1];
        g_topi[2 * n]     = i0;
        g_topi[2 * n + 1] = i1;
        g_topw[2 * n]     = p[i0] / s;
        g_topw[2 * n + 1] = p[i1] / s;
    }
}

// ---------------- routing bookkeeping ----------------------------------------
__global__ void route_build_kernel() {
    __shared__ int cnt[NEXP], cur[NEXP];
    const int t = threadIdx.x;
    if (t < NEXP) cnt[t] = 0;
    __syncthreads();
    for (int i = t; i < NPAIR; i += 1024) atomicAdd(&cnt[g_topi[i]], 1);
    __syncthreads();
    if (t == 0) {
        int s = 0;
        for (int e = 0; e < NEXP; e++) {
            g_counts[e] = cnt[e];
            g_offs[e] = s; cur[e] = s; s += cnt[e];
        }
        g_offs[NEXP] = s;
    }
    __syncthreads();
    for (int i = t; i < NPAIR; i += 1024) {
        int e = g_topi[i];
        int pos = atomicAdd(&cur[e], 1);   // per-row math order-free -> deterministic
        g_rows[pos] = i >> 1;
        g_map[i]    = pos;
    }
}

// ---------------- weight fp32 -> fp16 convert (all 3 tensors, 8 elems/thread) -
__global__ void wcvt_kernel(const float* __restrict__ W1,
                            const float* __restrict__ W3,
                            const float* __restrict__ W2) {
    const int which = blockIdx.y;
    const float* src = (which == 0) ? W1 : (which == 1) ? W3 : W2;
    __half* dst = (which == 0) ? g_w1f : (which == 1) ? g_w3f : g_w2f;
    size_t i = ((size_t)blockIdx.x * blockDim.x + threadIdx.x) * 8;
    float4 a = *(const float4*)(src + i);
    float4 b = *(const float4*)(src + i + 4);
    unsigned short h[8];
    h[0] = __half_as_ushort(__float2half_rn(a.x));
    h[1] = __half_as_ushort(__float2half_rn(a.y));
    h[2] = __half_as_ushort(__float2half_rn(a.z));
    h[3] = __half_as_ushort(__float2half_rn(a.w));
    h[4] = __half_as_ushort(__float2half_rn(b.x));
    h[5] = __half_as_ushort(__float2half_rn(b.y));
    h[6] = __half_as_ushort(__float2half_rn(b.z));
    h[7] = __half_as_ushort(__float2half_rn(b.w));
    uint4 o;
    o.x = (unsigned)h[0] | ((unsigned)h[1] << 16);
    o.y = (unsigned)h[2] | ((unsigned)h[3] << 16);
    o.z = (unsigned)h[4] | ((unsigned)h[5] << 16);
    o.w = (unsigned)h[6] | ((unsigned)h[7] << 16);
    *(uint4*)(dst + i) = o;
}

// ---------------- shared GEMM params ------------------------------------------
#define TM 128
#define TK 32
#define NSTG 3
#define ASTR 40

// ======================= fused W1+W3 GEMM =====================================
// CTA tile: M=128, N=64 per weight tensor. 2-term fp16: (Ah+Al) * B.
#define BSTRF 72

struct SmemF {
    __half Ah[NSTG][TM][ASTR];
    __half Al[NSTG][TM][ASTR];
    __half B1[NSTG][TK][BSTRF];
    __half B3[NSTG][TK][BSTRF];
    int srow[TM];
};
#define AL_OFF  (NSTG * TM * ASTR * 2)
#define SMEMF_BYTES ((int)sizeof(SmemF))

struct FragF {
    unsigned ah[2][4], al[2][4];
    unsigned b1[4][2], b3[4][2];
};

__device__ __forceinline__ void frag_load_f(FragF& f, SmemF& S, int s, int kk,
                                            int wm, int wn, int lane) {
#pragma unroll
    for (int mh = 0; mh < 2; mh++) {
        unsigned a = sm_u32(&S.Ah[s][wm + mh * 16 + (lane & 15)][kk + (lane >> 4) * 8]);
        ldsm4(f.ah[mh], a);
        ldsm4(f.al[mh], a + AL_OFF);
    }
#pragma unroll
    for (int ng = 0; ng < 2; ng++) {
        unsigned a1 = sm_u32(&S.B1[s][kk + (lane & 15)][wn + ng * 16 + (lane >> 4) * 8]);
        unsigned r[4];
        ldsm4t(r, a1);
        f.b1[2 * ng][0] = r[0]; f.b1[2 * ng][1] = r[1];
        f.b1[2 * ng + 1][0] = r[2]; f.b1[2 * ng + 1][1] = r[3];
        unsigned a3 = sm_u32(&S.B3[s][kk + (lane & 15)][wn + ng * 16 + (lane >> 4) * 8]);
        ldsm4t(r, a3);
        f.b3[2 * ng][0] = r[0]; f.b3[2 * ng][1] = r[1];
        f.b3[2 * ng + 1][0] = r[2]; f.b3[2 * ng + 1][1] = r[3];
    }
}

__device__ __forceinline__ void frag_mma_f(float acc1[2][4][4], float acc3[2][4][4],
                                           const FragF& f) {
#pragma unroll
    for (int mh = 0; mh < 2; mh++)
#pragma unroll
        for (int nf = 0; nf < 4; nf++) mma_f16(acc1[mh][nf], f.ah[mh], f.b1[nf]);
#pragma unroll
    for (int mh = 0; mh < 2; mh++)
#pragma unroll
        for (int nf = 0; nf < 4; nf++) mma_f16(acc3[mh][nf], f.ah[mh], f.b3[nf]);
#pragma unroll
    for (int mh = 0; mh < 2; mh++)
#pragma unroll
        for (int nf = 0; nf < 4; nf++) mma_f16(acc1[mh][nf], f.al[mh], f.b1[nf]);
#pragma unroll
    for (int mh = 0; mh < 2; mh++)
#pragma unroll
        for (int nf = 0; nf < 4; nf++) mma_f16(acc3[mh][nf], f.al[mh], f.b3[nf]);
}

__global__ __launch_bounds__(256) void gemm_fused13() {
    constexpr int Kd = CDIM;
    constexpr int Nd = HDIM;
    constexpr int NS = Kd / TK;
    extern __shared__ char sm_raw[];
    SmemF& S = *reinterpret_cast<SmemF*>(sm_raw);

    const int e    = blockIdx.z;
    const int cnt  = g_counts[e];
    const int row0 = blockIdx.y * TM;
    if (row0 >= cnt) return;
    const int mrows    = min(TM, cnt - row0);
    const int slotbase = g_offs[e] + row0;
    const int nt0      = blockIdx.x * 64;

    const int t = threadIdx.x;
    if (t < TM) {
        int m = min(t, mrows - 1);
        S.srow[t] = g_rows[slotbase + m];
    }
    __syncthreads();

    const int lane = t & 31;
    const int warp = t >> 5;
    const int wm = (warp & 3) * 32;
    const int wn = (warp >> 2) * 32;

    const int ar = t >> 1;
    const int ac = (t & 1) * 16;
    const size_t myrow = (size_t)S.srow[ar];
    const __half* pah = g_xh + myrow * Kd + ac;
    const __half* pal = g_xl + myrow * Kd + ac;
    const int bkr = t >> 3;          // 0..31
    const int bnc = (t & 7) * 8;     // 0..56
    const size_t boff = ((size_t)e * Kd + bkr) * Nd + nt0 + bnc;
    const __half* pb1 = g_w1f + boff;
    const __half* pb3 = g_w3f + boff;

    float acc1[2][4][4], acc3[2][4][4];
#pragma unroll
    for (int mi = 0; mi < 2; mi++)
#pragma unroll
        for (int ni = 0; ni < 4; ni++)
#pragma unroll
            for (int j = 0; j < 4; j++) { acc1[mi][ni][j] = 0.f; acc3[mi][ni][j] = 0.f; }

    auto load_stage = [&](int s, int k0) {
        unsigned sa = sm_u32(&S.Ah[s][ar][ac]);
        cp16(sa,               pah + k0);
        cp16(sa + 16,          pah + k0 + 8);
        cp16(sa + AL_OFF,      pal + k0);
        cp16(sa + AL_OFF + 16, pal + k0 + 8);
        const size_t ko = (size_t)k0 * Nd;
        cp16(sm_u32(&S.B1[s][bkr][bnc]), pb1 + ko);
        cp16(sm_u32(&S.B3[s][bkr][bnc]), pb3 + ko);
        CP_COMMIT();
    };

    load_stage(0, 0);
    load_stage(1, TK);
    CP_WAIT1();
    __syncthreads();
    FragF cur, nxt;
    frag_load_f(cur, S, 0, 0, wm, wn, lane);

#pragma unroll 1
    for (int j = 0; j < NS; j++) {
        const int s = j % NSTG;
        frag_load_f(nxt, S, s, 16, wm, wn, lane);
        frag_mma_f(acc1, acc3, cur);                    // (stage j, kk=0)
        if (j + 2 < NS) {
            load_stage((j + 2) % NSTG, (j + 2) * TK);
            CP_WAIT1();
        } else {
            CP_WAIT0();
        }
        __syncthreads();                                // publish stage j+1
        if (j + 1 < NS)
            frag_load_f(cur, S, (j + 1) % NSTG, 0, wm, wn, lane);
        frag_mma_f(acc1, acc3, nxt);                    // (stage j, kk=16)
    }

    // epilogue: h = silu(d1) * d3 -> fp16 hi/lo planes
    const int g = lane >> 2;
    const int q = lane & 3;
#pragma unroll
    for (int mh = 0; mh < 2; mh++)
#pragma unroll
        for (int nf = 0; nf < 4; nf++) {
            int r0 = wm + mh * 16 + g;
            int c  = nt0 + wn + nf * 8 + q * 2;
#pragma unroll
            for (int half = 0; half < 2; half++) {
                int r = r0 + half * 8;
                if (r >= mrows) continue;
                size_t orow = (size_t)(slotbase + r);
                float d10 = acc1[mh][nf][2 * half], d11 = acc1[mh][nf][2 * half + 1];
                float d30 = acc3[mh][nf][2 * half], d31 = acc3[mh][nf][2 * half + 1];
                float w0 = d10 / (1.f + __expf(-d10)) * d30;
                float w1 = d11 / (1.f + __expf(-d11)) * d31;
                unsigned short h0, l0, h1, l1;
                split_f16(w0, h0, l0);
                split_f16(w1, h1, l1);
                *(unsigned*)(g_hh + orow * HDIM + c) = (unsigned)h0 | ((unsigned)h1 << 16);
                *(unsigned*)(g_hl + orow * HDIM + c) = (unsigned)l0 | ((unsigned)l1 << 16);
            }
        }
}

// ======================= W2 GEMM (hidden -> y) ================================
#define TN2 128
#define BSTR2 136

struct Smem2 {
    __half Ah[NSTG][TM][ASTR];
    __half Al[NSTG][TM][ASTR];
    __half B[NSTG][TK][BSTR2];
    int srow[TM];
};
#define SMEM2_BYTES ((int)sizeof(Smem2))

struct Frag2 {
    unsigned ah[2][4], al[2][4];
    unsigned bh[8][2];
};

__device__ __forceinline__ void frag_load_2(Frag2& f, Smem2& S, int s, int kk,
                                            int wm, int wn, int lane) {
#pragma unroll
    for (int mh = 0; mh < 2; mh++) {
        unsigned a = sm_u32(&S.Ah[s][wm + mh * 16 + (lane & 15)][kk + (lane >> 4) * 8]);
        ldsm4(f.ah[mh], a);
        ldsm4(f.al[mh], a + AL_OFF);
    }
#pragma unroll
    for (int ng = 0; ng < 4; ng++) {
        unsigned a = sm_u32(&S.B[s][kk + (lane & 15)][wn + ng * 16 + (lane >> 4) * 8]);
        unsigned r[4];
        ldsm4t(r, a);
        f.bh[2 * ng][0] = r[0]; f.bh[2 * ng][1] = r[1];
        f.bh[2 * ng + 1][0] = r[2]; f.bh[2 * ng + 1][1] = r[3];
    }
}

__device__ __forceinline__ void frag_mma_2(float acc[2][8][4], const Frag2& f) {
#pragma unroll
    for (int mh = 0; mh < 2; mh++)
#pragma unroll
        for (int nf = 0; nf < 8; nf++) mma_f16(acc[mh][nf], f.ah[mh], f.bh[nf]);
#pragma unroll
    for (int mh = 0; mh < 2; mh++)
#pragma unroll
        for (int nf = 0; nf < 8; nf++) mma_f16(acc[mh][nf], f.al[mh], f.bh[nf]);
}

__global__ __launch_bounds__(256) void gemm_w2() {
    constexpr int Kd = HDIM;
    constexpr int Nd = CDIM;
    constexpr int NS = Kd / TK;
    extern __shared__ char sm_raw[];
    Smem2& S = *reinterpret_cast<Smem2*>(sm_raw);

    const int e    = blockIdx.z;
    const int cnt  = g_counts[e];
    const int row0 = blockIdx.y * TM;
    if (row0 >= cnt) return;
    const int mrows    = min(TM, cnt - row0);
    const int slotbase = g_offs[e] + row0;
    const int nt0      = blockIdx.x * TN2;

    const int t = threadIdx.x;
    if (t < TM) S.srow[t] = slotbase + min(t, mrows - 1);
    __syncthreads();

    const int lane = t & 31;
    const int warp = t >> 5;
    const int wm = (warp & 3) * 32;
    const int wn = (warp >> 2) * 64;

    const int ar = t >> 1;
    const int ac = (t & 1) * 16;
    const size_t myrow = (size_t)S.srow[ar];
    const __half* pah = g_hh + myrow * Kd + ac;
    const __half* pal = g_hl + myrow * Kd + ac;
    const int bkr = t >> 3;
    const int bnc = (t & 7) * 16;
    const __half* pb = g_w2f + ((size_t)e * Kd + bkr) * Nd + nt0 + bnc;

    float acc[2][8][4];
#pragma unroll
    for (int mi = 0; mi < 2; mi++)
#pragma unroll
        for (int ni = 0; ni < 8; ni++)
#pragma unroll
            for (int j = 0; j < 4; j++) acc[mi][ni][j] = 0.f;

    auto load_stage = [&](int s, int k0) {
        unsigned sa = sm_u32(&S.Ah[s][ar][ac]);
        cp16(sa,               pah + k0);
        cp16(sa + 16,          pah + k0 + 8);
        cp16(sa + AL_OFF,      pal + k0);
        cp16(sa + AL_OFF + 16, pal + k0 + 8);
        unsigned sb = sm_u32(&S.B[s][bkr][bnc]);
        const __half* bh = pb + (size_t)k0 * Nd;
        cp16(sb,      bh);
        cp16(sb + 16, bh + 8);
        CP_COMMIT();
    };

    load_stage(0, 0);
    load_stage(1, TK);
    CP_WAIT1();
    __syncthreads();
    Frag2 cur, nxt;
    frag_load_2(cur, S, 0, 0, wm, wn, lane);

#pragma unroll 1
    for (int j = 0; j < NS; j++) {
        const int s = j % NSTG;
        frag_load_2(nxt, S, s, 16, wm, wn, lane);
        frag_mma_2(acc, cur);
        if (j + 2 < NS) {
            load_stage((j + 2) % NSTG, (j + 2) * TK);
            CP_WAIT1();
        } else {
            CP_WAIT0();
        }
        __syncthreads();
        if (j + 1 < NS)
            frag_load_2(cur, S, (j + 1) % NSTG, 0, wm, wn, lane);
        frag_mma_2(acc, nxt);
    }

    const int g = lane >> 2;
    const int q = lane & 3;
#pragma unroll
    for (int mh = 0; mh < 2; mh++)
#pragma unroll
        for (int nf = 0; nf < 8; nf++) {
            int r0 = wm + mh * 16 + g;
            int c  = nt0 + wn + nf * 8 + q * 2;
#pragma unroll
            for (int half = 0; half < 2; half++) {
                int r = r0 + half * 8;
                if (r >= mrows) continue;
                size_t orow = (size_t)(slotbase + r);
                float* p = g_y + orow * CDIM + c;
                p[0] = acc[mh][nf][2 * half];
                p[1] = acc[mh][nf][2 * half + 1];
            }
        }
}

// ---------------- final gather-combine --------------------------------------
__global__ void combine_kernel(float* __restrict__ out) {
    int idx = blockIdx.x * blockDim.x + threadIdx.x;
    int n  = idx >> 8;
    int c4 = (idx & 255) << 2;
    int p0 = g_map[2 * n], p1 = g_map[2 * n + 1];
    float w0 = g_topw[2 * n], w1 = g_topw[2 * n + 1];
    float4 y0 = *(const float4*)(g_y + (size_t)p0 * CDIM + c4);
    float4 y1 = *(const float4*)(g_y + (size_t)p1 * CDIM + c4);
    float4 r;
    r.x = w0 * y0.x + w1 * y1.x;
    r.y = w0 * y0.y + w1 * y1.y;
    r.z = w0 * y0.z + w1 * y1.z;
    r.w = w0 * y0.w + w1 * y1.w;
    *(float4*)(out + (size_t)n * CDIM + c4) = r;
}

// ---------------- launch ------------------------------------------------------
extern "C" void kernel_launch(void* const* d_in, const int* in_sizes, int n_in,
                              void* d_out, int out_size) {
    const float* x  = (const float*)d_in[0];
    const float* Wg = (const float*)d_in[1];
    const float* W1 = (const float*)d_in[2];
    const float* W3 = (const float*)d_in[3];
    const float* W2 = (const float*)d_in[4];
    float* out = (float*)d_out;

    cudaFuncSetAttribute(gemm_fused13, cudaFuncAttributeMaxDynamicSharedMemorySize, SMEMF_BYTES);
    cudaFuncSetAttribute(gemm_w2, cudaFuncAttributeMaxDynamicSharedMemorySize, SMEM2_BYTES);

    const size_t WELEMS = (size_t)NEXP * CDIM * HDIM;   // 33.5M per tensor

    // launch index 3 = gemm_fused13 (ncu captures index 3)
    wcvt_kernel<<<dim3((unsigned)(WELEMS / 8 / 256), 3), 256>>>(W1, W3, W2);  // 0
    router_kernel<<<NTOK, 256>>>(x, Wg);                                      // 1
    route_build_kernel<<<1, 1024>>>();                                        // 2
    gemm_fused13<<<dim3(HDIM / 64, NTOK / TM, NEXP), 256, SMEMF_BYTES>>>();   // 3
    gemm_w2<<<dim3(CDIM / TN2, NTOK / TM, NEXP), 256, SMEM2_BYTES>>>();       // 4
    combine_kernel<<<(NTOK * (CDIM / 4)) / 256, 256>>>(out);                  // 5
}

// round 10
// speedup vs baseline: 1.7238x; 1.0574x over previous
#include <cuda_runtime.h>
#include <cuda_fp16.h>
#include <math.h>

#define NTOK 4096
#define CDIM 1024
#define HDIM 4096
#define NEXP 8
#define NPAIR (NTOK * 2)

// ---------------- scratch (device globals) -----------------------------------
__device__ int   g_counts[NEXP];
__device__ int   g_offs[NEXP + 1];
__device__ int   g_topi[NPAIR];
__device__ float g_topw[NPAIR];
__device__ int   g_rows[NPAIR];
__device__ int   g_map[NPAIR];
__device__ __half g_xh[(size_t)NTOK * CDIM];
__device__ __half g_xl[(size_t)NTOK * CDIM];
__device__ __half g_hh[(size_t)NPAIR * HDIM];
__device__ __half g_hl[(size_t)NPAIR * HDIM];
__device__ float g_y [(size_t)NPAIR * CDIM];
__device__ __half g_w1f[(size_t)NEXP * CDIM * HDIM];
__device__ __half g_w3f[(size_t)NEXP * CDIM * HDIM];
__device__ __half g_w2f[(size_t)NEXP * HDIM * CDIM];

// ---------------- helpers -----------------------------------------------------
__device__ __forceinline__ unsigned sm_u32(const void* p) {
    return (unsigned)__cvta_generic_to_shared(p);
}
__device__ __forceinline__ void cp16(unsigned s, const void* g) {
    asm volatile("cp.async.cg.shared.global [%0], [%1], 16;\n" :: "r"(s), "l"(g));
}
#define CP_COMMIT() asm volatile("cp.async.commit_group;" ::: "memory")
#define CP_WAIT1()  asm volatile("cp.async.wait_group 1;" ::: "memory")
#define CP_WAIT0()  asm volatile("cp.async.wait_group 0;" ::: "memory")
__device__ __forceinline__ void ldsm4(unsigned* r, unsigned a) {
    asm volatile("ldmatrix.sync.aligned.m8n8.x4.shared.b16 {%0,%1,%2,%3}, [%4];"
                 : "=r"(r[0]), "=r"(r[1]), "=r"(r[2]), "=r"(r[3]) : "r"(a));
}
__device__ __forceinline__ void ldsm4t(unsigned* r, unsigned a) {
    asm volatile("ldmatrix.sync.aligned.m8n8.x4.trans.shared.b16 {%0,%1,%2,%3}, [%4];"
                 : "=r"(r[0]), "=r"(r[1]), "=r"(r[2]), "=r"(r[3]) : "r"(a));
}
__device__ __forceinline__ void mma_f16(float* d, const unsigned* a, const unsigned* b) {
    asm volatile(
        "mma.sync.aligned.m16n8k16.row.col.f32.f16.f16.f32 "
        "{%0,%1,%2,%3}, {%4,%5,%6,%7}, {%8,%9}, {%0,%1,%2,%3};\n"
        : "+f"(d[0]), "+f"(d[1]), "+f"(d[2]), "+f"(d[3])
        : "r"(a[0]), "r"(a[1]), "r"(a[2]), "r"(a[3]), "r"(b[0]), "r"(b[1]));
}
__device__ __forceinline__ void split_f16(float v, unsigned short& h, unsigned short& l) {
    __half hb = __float2half_rn(v);
    __half lb = __float2half_rn(v - __half2float(hb));
    h = __half_as_ushort(hb);
    l = __half_as_ushort(lb);
}

// ---------------- router (fused with x hi/lo fp16 split) ----------------------
__global__ void router_kernel(const float* __restrict__ x,
                              const float* __restrict__ Wg) {
    const int n = blockIdx.x;
    const int t = threadIdx.x;
    const int c0 = t * 4;
    const float4 v = *(const float4*)(x + (size_t)n * CDIM + c0);

    {
        unsigned short h[4], l[4];
        split_f16(v.x, h[0], l[0]); split_f16(v.y, h[1], l[1]);
        split_f16(v.z, h[2], l[2]); split_f16(v.w, h[3], l[3]);
        uint2 hp, lp;
        hp.x = (unsigned)h[0] | ((unsigned)h[1] << 16);
        hp.y = (unsigned)h[2] | ((unsigned)h[3] << 16);
        lp.x = (unsigned)l[0] | ((unsigned)l[1] << 16);
        lp.y = (unsigned)l[2] | ((unsigned)l[3] << 16);
        *(uint2*)(g_xh + (size_t)n * CDIM + c0) = hp;
        *(uint2*)(g_xl + (size_t)n * CDIM + c0) = lp;
    }

    float acc[NEXP];
#pragma unroll
    for (int e = 0; e < NEXP; e++) {
        acc[e] = v.x * Wg[(c0 + 0) * NEXP + e] + v.y * Wg[(c0 + 1) * NEXP + e]
               + v.z * Wg[(c0 + 2) * NEXP + e] + v.w * Wg[(c0 + 3) * NEXP + e];
    }
#pragma unroll
    for (int off = 16; off; off >>= 1)
#pragma unroll
        for (int e = 0; e < NEXP; e++)
            acc[e] += __shfl_down_sync(0xffffffffu, acc[e], off);

    __shared__ float red[8][NEXP];
    if ((t & 31) == 0)
#pragma unroll
        for (int e = 0; e < NEXP; e++) red[t >> 5][e] = acc[e];
    __syncthreads();
    if (t == 0) {
        float l[NEXP];
#pragma unroll
        for (int e = 0; e < NEXP; e++) {
            float s = 0.f;
#pragma unroll
            for (int w = 0; w < 8; w++) s += red[w][e];   // fixed order
            l[e] = s;
        }
        float mx = l[0];
#pragma unroll
        for (int e = 1; e < NEXP; e++) mx = fmaxf(mx, l[e]);
        float p[NEXP];
#pragma unroll
        for (int e = 0; e < NEXP; e++) p[e] = expf(l[e] - mx);
        int i0 = 0;
#pragma unroll
        for (int e = 1; e < NEXP; e++) if (p[e] > p[i0]) i0 = e;
        int i1 = (i0 == 0) ? 1 : 0;
#pragma unroll
        for (int e = 0; e < NEXP; e++) if (e != i0 && p[e] > p[i1]) i1 = e;
        float s = p[i0] + p[i1];
        g_topi[2 * n]     = i0;
        g_topi[2 * n + 1] = i1;
        g_topw[2 * n]     = p[i0] / s;
        g_topw[2 * n + 1] = p[i1] / s;
    }
}

// ---------------- routing bookkeeping ----------------------------------------
__global__ void route_build_kernel() {
    __shared__ int cnt[NEXP], cur[NEXP];
    const int t = threadIdx.x;
    if (t < NEXP) cnt[t] = 0;
    __syncthreads();
    for (int i = t; i < NPAIR; i += 1024) atomicAdd(&cnt[g_topi[i]], 1);
    __syncthreads();
    if (t == 0) {
        int s = 0;
        for (int e = 0; e < NEXP; e++) {
            g_counts[e] = cnt[e];
            g_offs[e] = s; cur[e] = s; s += cnt[e];
        }
        g_offs[NEXP] = s;
    }
    __syncthreads();
    for (int i = t; i < NPAIR; i += 1024) {
        int e = g_topi[i];
        int pos = atomicAdd(&cur[e], 1);   // per-row math order-free -> deterministic
        g_rows[pos] = i >> 1;
        g_map[i]    = pos;
    }
}

// ---------------- weight fp32 -> fp16 convert ---------------------------------
__global__ void wcvt_kernel(const float* __restrict__ W1,
                            const float* __restrict__ W3,
                            const float* __restrict__ W2) {
    const int which = blockIdx.y;
    const float* src = (which == 0) ? W1 : (which == 1) ? W3 : W2;
    __half* dst = (which == 0) ? g_w1f : (which == 1) ? g_w3f : g_w2f;
    size_t i = ((size_t)blockIdx.x * blockDim.x + threadIdx.x) * 8;
    float4 a = *(const float4*)(src + i);
    float4 b = *(const float4*)(src + i + 4);
    unsigned short h[8];
    h[0] = __half_as_ushort(__float2half_rn(a.x));
    h[1] = __half_as_ushort(__float2half_rn(a.y));
    h[2] = __half_as_ushort(__float2half_rn(a.z));
    h[3] = __half_as_ushort(__float2half_rn(a.w));
    h[4] = __half_as_ushort(__float2half_rn(b.x));
    h[5] = __half_as_ushort(__float2half_rn(b.y));
    h[6] = __half_as_ushort(__float2half_rn(b.z));
    h[7] = __half_as_ushort(__float2half_rn(b.w));
    uint4 o;
    o.x = (unsigned)h[0] | ((unsigned)h[1] << 16);
    o.y = (unsigned)h[2] | ((unsigned)h[3] << 16);
    o.z = (unsigned)h[4] | ((unsigned)h[5] << 16);
    o.w = (unsigned)h[6] | ((unsigned)h[7] << 16);
    *(uint4*)(dst + i) = o;
}

// ---------------- shared GEMM params ------------------------------------------
#define TM 128
#define TK 32
#define NSTG 3
#define ASTR 40

// ======================= fused W1+W3 GEMM =====================================
#define BSTRF 72

struct SmemF {
    __half Ah[NSTG][TM][ASTR];
    __half Al[NSTG][TM][ASTR];
    __half B1[NSTG][TK][BSTRF];
    __half B3[NSTG][TK][BSTRF];
    int srow[TM];
};
#define AL_OFF  (NSTG * TM * ASTR * 2)
#define SMEMF_BYTES ((int)sizeof(SmemF))

struct FragF {
    unsigned ah[2][4], al[2][4];
    unsigned b1[4][2], b3[4][2];
};

__device__ __forceinline__ void frag_load_f(FragF& f, SmemF& S, int s, int kk,
                                            int wm, int wn, int lane) {
#pragma unroll
    for (int mh = 0; mh < 2; mh++) {
        unsigned a = sm_u32(&S.Ah[s][wm + mh * 16 + (lane & 15)][kk + (lane >> 4) * 8]);
        ldsm4(f.ah[mh], a);
        ldsm4(f.al[mh], a + AL_OFF);
    }
#pragma unroll
    for (int ng = 0; ng < 2; ng++) {
        unsigned a1 = sm_u32(&S.B1[s][kk + (lane & 15)][wn + ng * 16 + (lane >> 4) * 8]);
        unsigned r[4];
        ldsm4t(r, a1);
        f.b1[2 * ng][0] = r[0]; f.b1[2 * ng][1] = r[1];
        f.b1[2 * ng + 1][0] = r[2]; f.b1[2 * ng + 1][1] = r[3];
        unsigned a3 = sm_u32(&S.B3[s][kk + (lane & 15)][wn + ng * 16 + (lane >> 4) * 8]);
        ldsm4t(r, a3);
        f.b3[2 * ng][0] = r[0]; f.b3[2 * ng][1] = r[1];
        f.b3[2 * ng + 1][0] = r[2]; f.b3[2 * ng + 1][1] = r[3];
    }
}

__device__ __forceinline__ void frag_mma_f(float acc1[2][4][4], float acc3[2][4][4],
                                           const FragF& f) {
#pragma unroll
    for (int mh = 0; mh < 2; mh++)
#pragma unroll
        for (int nf = 0; nf < 4; nf++) mma_f16(acc1[mh][nf], f.ah[mh], f.b1[nf]);
#pragma unroll
    for (int mh = 0; mh < 2; mh++)
#pragma unroll
        for (int nf = 0; nf < 4; nf++) mma_f16(acc3[mh][nf], f.ah[mh], f.b3[nf]);
#pragma unroll
    for (int mh = 0; mh < 2; mh++)
#pragma unroll
        for (int nf = 0; nf < 4; nf++) mma_f16(acc1[mh][nf], f.al[mh], f.b1[nf]);
#pragma unroll
    for (int mh = 0; mh < 2; mh++)
#pragma unroll
        for (int nf = 0; nf < 4; nf++) mma_f16(acc3[mh][nf], f.al[mh], f.b3[nf]);
}

__global__ __launch_bounds__(256, 2) void gemm_fused13() {
    constexpr int Kd = CDIM;
    constexpr int Nd = HDIM;
    constexpr int NS = Kd / TK;
    extern __shared__ char sm_raw[];
    SmemF& S = *reinterpret_cast<SmemF*>(sm_raw);

    const int e    = blockIdx.z;
    const int cnt  = g_counts[e];
    const int row0 = blockIdx.y * TM;
    if (row0 >= cnt) return;
    const int mrows    = min(TM, cnt - row0);
    const int slotbase = g_offs[e] + row0;
    const int nt0      = blockIdx.x * 64;

    const int t = threadIdx.x;
    if (t < TM) {
        int m = min(t, mrows - 1);
        S.srow[t] = g_rows[slotbase + m];
    }
    __syncthreads();

    const int lane = t & 31;
    const int warp = t >> 5;
    const int wm = (warp & 3) * 32;
    const int wn = (warp >> 2) * 32;

    const int ar = t >> 1;
    const int ac = (t & 1) * 16;
    const size_t myrow = (size_t)S.srow[ar];
    const __half* pah = g_xh + myrow * Kd + ac;
    const __half* pal = g_xl + myrow * Kd + ac;
    const int bkr = t >> 3;          // 0..31
    const int bnc = (t & 7) * 8;     // 0..56
    const size_t boff = ((size_t)e * Kd + bkr) * Nd + nt0 + bnc;
    const __half* pb1 = g_w1f + boff;
    const __half* pb3 = g_w3f + boff;

    float acc1[2][4][4], acc3[2][4][4];
#pragma unroll
    for (int mi = 0; mi < 2; mi++)
#pragma unroll
        for (int ni = 0; ni < 4; ni++)
#pragma unroll
            for (int j = 0; j < 4; j++) { acc1[mi][ni][j] = 0.f; acc3[mi][ni][j] = 0.f; }

    auto load_stage = [&](int s, int k0) {
        unsigned sa = sm_u32(&S.Ah[s][ar][ac]);
        cp16(sa,               pah + k0);
        cp16(sa + 16,          pah + k0 + 8);
        cp16(sa + AL_OFF,      pal + k0);
        cp16(sa + AL_OFF + 16, pal + k0 + 8);
        const size_t ko = (size_t)k0 * Nd;
        cp16(sm_u32(&S.B1[s][bkr][bnc]), pb1 + ko);
        cp16(sm_u32(&S.B3[s][bkr][bnc]), pb3 + ko);
        CP_COMMIT();
    };

    load_stage(0, 0);
    load_stage(1, TK);

#pragma unroll 1
    for (int j = 0; j < NS; j++) {
        const int s = j % NSTG;
        if (j == NS - 1) { CP_WAIT0(); } else { CP_WAIT1(); }   // stage j resident
        __syncthreads();     // publish; also guards slot (j-1)%3 refill below
        if (j + 2 < NS) load_stage((j + 2) % NSTG, (j + 2) * TK);
        FragF f;
        frag_load_f(f, S, s, 0, wm, wn, lane);
        frag_mma_f(acc1, acc3, f);
        frag_load_f(f, S, s, 16, wm, wn, lane);
        frag_mma_f(acc1, acc3, f);
    }

    // epilogue: h = silu(d1) * d3 -> fp16 hi/lo planes
    const int g = lane >> 2;
    const int q = lane & 3;
#pragma unroll
    for (int mh = 0; mh < 2; mh++)
#pragma unroll
        for (int nf = 0; nf < 4; nf++) {
            int r0 = wm + mh * 16 + g;
            int c  = nt0 + wn + nf * 8 + q * 2;
#pragma unroll
            for (int half = 0; half < 2; half++) {
                int r = r0 + half * 8;
                if (r >= mrows) continue;
                size_t orow = (size_t)(slotbase + r);
                float d10 = acc1[mh][nf][2 * half], d11 = acc1[mh][nf][2 * half + 1];
                float d30 = acc3[mh][nf][2 * half], d31 = acc3[mh][nf][2 * half + 1];
                float w0 = d10 / (1.f + __expf(-d10)) * d30;
                float w1 = d11 / (1.f + __expf(-d11)) * d31;
                unsigned short h0, l0, h1, l1;
                split_f16(w0, h0, l0);
                split_f16(w1, h1, l1);
                *(unsigned*)(g_hh + orow * HDIM + c) = (unsigned)h0 | ((unsigned)h1 << 16);
                *(unsigned*)(g_hl + orow * HDIM + c) = (unsigned)l0 | ((unsigned)l1 << 16);
            }
        }
}

// ======================= W2 GEMM (hidden -> y) ================================
#define TN2 128
#define BSTR2 136

struct Smem2 {
    __half Ah[NSTG][TM][ASTR];
    __half Al[NSTG][TM][ASTR];
    __half B[NSTG][TK][BSTR2];
    int srow[TM];
};
#define SMEM2_BYTES ((int)sizeof(Smem2))

struct Frag2 {
    unsigned ah[2][4], al[2][4];
    unsigned bh[8][2];
};

__device__ __forceinline__ void frag_load_2(Frag2& f, Smem2& S, int s, int kk,
                                            int wm, int wn, int lane) {
#pragma unroll
    for (int mh = 0; mh < 2; mh++) {
        unsigned a = sm_u32(&S.Ah[s][wm + mh * 16 + (lane & 15)][kk + (lane >> 4) * 8]);
        ldsm4(f.ah[mh], a);
        ldsm4(f.al[mh], a + AL_OFF);
    }
#pragma unroll
    for (int ng = 0; ng < 4; ng++) {
        unsigned a = sm_u32(&S.B[s][kk + (lane & 15)][wn + ng * 16 + (lane >> 4) * 8]);
        unsigned r[4];
        ldsm4t(r, a);
        f.bh[2 * ng][0] = r[0]; f.bh[2 * ng][1] = r[1];
        f.bh[2 * ng + 1][0] = r[2]; f.bh[2 * ng + 1][1] = r[3];
    }
}

__device__ __forceinline__ void frag_mma_2(float acc[2][8][4], const Frag2& f) {
#pragma unroll
    for (int mh = 0; mh < 2; mh++)
#pragma unroll
        for (int nf = 0; nf < 8; nf++) mma_f16(acc[mh][nf], f.ah[mh], f.bh[nf]);
#pragma unroll
    for (int mh = 0; mh < 2; mh++)
#pragma unroll
        for (int nf = 0; nf < 8; nf++) mma_f16(acc[mh][nf], f.al[mh], f.bh[nf]);
}

__global__ __launch_bounds__(256, 2) void gemm_w2() {
    constexpr int Kd = HDIM;
    constexpr int Nd = CDIM;
    constexpr int NS = Kd / TK;
    extern __shared__ char sm_raw[];
    Smem2& S = *reinterpret_cast<Smem2*>(sm_raw);

    const int e    = blockIdx.z;
    const int cnt  = g_counts[e];
    const int row0 = blockIdx.y * TM;
    if (row0 >= cnt) return;
    const int mrows    = min(TM, cnt - row0);
    const int slotbase = g_offs[e] + row0;
    const int nt0      = blockIdx.x * TN2;

    const int t = threadIdx.x;
    if (t < TM) S.srow[t] = slotbase + min(t, mrows - 1);
    __syncthreads();

    const int lane = t & 31;
    const int warp = t >> 5;
    const int wm = (warp & 3) * 32;
    const int wn = (warp >> 2) * 64;

    const int ar = t >> 1;
    const int ac = (t & 1) * 16;
    const size_t myrow = (size_t)S.srow[ar];
    const __half* pah = g_hh + myrow * Kd + ac;
    const __half* pal = g_hl + myrow * Kd + ac;
    const int bkr = t >> 3;
    const int bnc = (t & 7) * 16;
    const __half* pb = g_w2f + ((size_t)e * Kd + bkr) * Nd + nt0 + bnc;

    float acc[2][8][4];
#pragma unroll
    for (int mi = 0; mi < 2; mi++)
#pragma unroll
        for (int ni = 0; ni < 8; ni++)
#pragma unroll
            for (int j = 0; j < 4; j++) acc[mi][ni][j] = 0.f;

    auto load_stage = [&](int s, int k0) {
        unsigned sa = sm_u32(&S.Ah[s][ar][ac]);
        cp16(sa,               pah + k0);
        cp16(sa + 16,          pah + k0 + 8);
        cp16(sa + AL_OFF,      pal + k0);
        cp16(sa + AL_OFF + 16, pal + k0 + 8);
        unsigned sb = sm_u32(&S.B[s][bkr][bnc]);
        const __half* bh = pb + (size_t)k0 * Nd;
        cp16(sb,      bh);
        cp16(sb + 16, bh + 8);
        CP_COMMIT();
    };

    load_stage(0, 0);
    load_stage(1, TK);

#pragma unroll 1
    for (int j = 0; j < NS; j++) {
        const int s = j % NSTG;
        if (j == NS - 1) { CP_WAIT0(); } else { CP_WAIT1(); }
        __syncthreads();
        if (j + 2 < NS) load_stage((j + 2) % NSTG, (j + 2) * TK);
        Frag2 f;
        frag_load_2(f, S, s, 0, wm, wn, lane);
        frag_mma_2(acc, f);
        frag_load_2(f, S, s, 16, wm, wn, lane);
        frag_mma_2(acc, f);
    }

    const int g = lane >> 2;
    const int q = lane & 3;
#pragma unroll
    for (int mh = 0; mh < 2; mh++)
#pragma unroll
        for (int nf = 0; nf < 8; nf++) {
            int r0 = wm + mh * 16 + g;
            int c  = nt0 + wn + nf * 8 + q * 2;
#pragma unroll
            for (int half = 0; half < 2; half++) {
                int r = r0 + half * 8;
                if (r >= mrows) continue;
                size_t orow = (size_t)(slotbase + r);
                float* p = g_y + orow * CDIM + c;
                p[0] = acc[mh][nf][2 * half];
                p[1] = acc[mh][nf][2 * half + 1];
            }
        }
}

// ---------------- final gather-combine --------------------------------------
__global__ void combine_kernel(float* __restrict__ out) {
    int idx = blockIdx.x * blockDim.x + threadIdx.x;
    int n  = idx >> 8;
    int c4 = (idx & 255) << 2;
    int p0 = g_map[2 * n], p1 = g_map[2 * n + 1];
    float w0 = g_topw[2 * n], w1 = g_topw[2 * n + 1];
    float4 y0 = *(const float4*)(g_y + (size_t)p0 * CDIM + c4);
    float4 y1 = *(const float4*)(g_y + (size_t)p1 * CDIM + c4);
    float4 r;
    r.x = w0 * y0.x + w1 * y1.x;
    r.y = w0 * y0.y + w1 * y1.y;
    r.z = w0 * y0.z + w1 * y1.z;
    r.w = w0 * y0.w + w1 * y1.w;
    *(float4*)(out + (size_t)n * CDIM + c4) = r;
}

// ---------------- launch ------------------------------------------------------
extern "C" void kernel_launch(void* const* d_in, const int* in_sizes, int n_in,
                              void* d_out, int out_size) {
    const float* x  = (const float*)d_in[0];
    const float* Wg = (const float*)d_in[1];
    const float* W1 = (const float*)d_in[2];
    const float* W3 = (const float*)d_in[3];
    const float* W2 = (const float*)d_in[4];
    float* out = (float*)d_out;

    cudaFuncSetAttribute(gemm_fused13, cudaFuncAttributeMaxDynamicSharedMemorySize, SMEMF_BYTES);
    cudaFuncSetAttribute(gemm_w2, cudaFuncAttributeMaxDynamicSharedMemorySize, SMEM2_BYTES);

    const size_t WELEMS = (size_t)NEXP * CDIM * HDIM;

    // launch index 3 = gemm_fused13 (ncu captures index 3)
    wcvt_kernel<<<dim3((unsigned)(WELEMS / 8 / 256), 3), 256>>>(W1, W3, W2);  // 0
    router_kernel<<<NTOK, 256>>>(x, Wg);                                      // 1
    route_build_kernel<<<1, 1024>>>();                                        // 2
    gemm_fused13<<<dim3(HDIM / 64, NTOK / TM, NEXP), 256, SMEMF_BYTES>>>();   // 3
    gemm_w2<<<dim3(CDIM / TN2, NTOK / TM, NEXP), 256, SMEM2_BYTES>>>();       // 4
    combine_kernel<<<(NTOK * (CDIM / 4)) / 256, 256>>>(out);                  // 5
}

// round 11
// speedup vs baseline: 2.0181x; 1.1708x over previous
#include <cuda_runtime.h>
#include <cuda_fp16.h>
#include <math.h>

#define NTOK 4096
#define CDIM 1024
#define HDIM 4096
#define NEXP 8
#define NPAIR (NTOK * 2)

// ---------------- scratch (device globals) -----------------------------------
__device__ int   g_counts[NEXP];
__device__ int   g_offs[NEXP + 1];
__device__ int   g_topi[NPAIR];
__device__ float g_topw[NPAIR];
__device__ int   g_rows[NPAIR];
__device__ int   g_map[NPAIR];
__device__ __half g_xh[(size_t)NTOK * CDIM];     // x hi plane
__device__ __half g_xl[(size_t)NTOK * CDIM];     // x lo plane
__device__ __half g_hh[(size_t)NPAIR * HDIM];    // hidden (single fp16 plane)
__device__ float g_y [(size_t)NPAIR * CDIM];
__device__ __half g_w1f[(size_t)NEXP * CDIM * HDIM];
__device__ __half g_w3f[(size_t)NEXP * CDIM * HDIM];
__device__ __half g_w2f[(size_t)NEXP * HDIM * CDIM];

// ---------------- helpers -----------------------------------------------------
__device__ __forceinline__ unsigned sm_u32(const void* p) {
    return (unsigned)__cvta_generic_to_shared(p);
}
__device__ __forceinline__ void cp16(unsigned s, const void* g) {
    asm volatile("cp.async.cg.shared.global [%0], [%1], 16;\n" :: "r"(s), "l"(g));
}
#define CP_COMMIT() asm volatile("cp.async.commit_group;" ::: "memory")
#define CP_WAIT1()  asm volatile("cp.async.wait_group 1;" ::: "memory")
#define CP_WAIT0()  asm volatile("cp.async.wait_group 0;" ::: "memory")
__device__ __forceinline__ void ldsm4(unsigned* r, unsigned a) {
    asm volatile("ldmatrix.sync.aligned.m8n8.x4.shared.b16 {%0,%1,%2,%3}, [%4];"
                 : "=r"(r[0]), "=r"(r[1]), "=r"(r[2]), "=r"(r[3]) : "r"(a));
}
__device__ __forceinline__ void ldsm4t(unsigned* r, unsigned a) {
    asm volatile("ldmatrix.sync.aligned.m8n8.x4.trans.shared.b16 {%0,%1,%2,%3}, [%4];"
                 : "=r"(r[0]), "=r"(r[1]), "=r"(r[2]), "=r"(r[3]) : "r"(a));
}
__device__ __forceinline__ void mma_f16(float* d, const unsigned* a, const unsigned* b) {
    asm volatile(
        "mma.sync.aligned.m16n8k16.row.col.f32.f16.f16.f32 "
        "{%0,%1,%2,%3}, {%4,%5,%6,%7}, {%8,%9}, {%0,%1,%2,%3};\n"
        : "+f"(d[0]), "+f"(d[1]), "+f"(d[2]), "+f"(d[3])
        : "r"(a[0]), "r"(a[1]), "r"(a[2]), "r"(a[3]), "r"(b[0]), "r"(b[1]));
}
__device__ __forceinline__ void split_f16(float v, unsigned short& h, unsigned short& l) {
    __half hb = __float2half_rn(v);
    __half lb = __float2half_rn(v - __half2float(hb));
    h = __half_as_ushort(hb);
    l = __half_as_ushort(lb);
}

// ---------------- router (fused with x hi/lo fp16 split) ----------------------
__global__ void router_kernel(const float* __restrict__ x,
                              const float* __restrict__ Wg) {
    const int n = blockIdx.x;
    const int t = threadIdx.x;
    const int c0 = t * 4;
    const float4 v = *(const float4*)(x + (size_t)n * CDIM + c0);

    {
        unsigned short h[4], l[4];
        split_f16(v.x, h[0], l[0]); split_f16(v.y, h[1], l[1]);
        split_f16(v.z, h[2], l[2]); split_f16(v.w, h[3], l[3]);
        uint2 hp, lp;
        hp.x = (unsigned)h[0] | ((unsigned)h[1] << 16);
        hp.y = (unsigned)h[2] | ((unsigned)h[3] << 16);
        lp.x = (unsigned)l[0] | ((unsigned)l[1] << 16);
        lp.y = (unsigned)l[2] | ((unsigned)l[3] << 16);
        *(uint2*)(g_xh + (size_t)n * CDIM + c0) = hp;
        *(uint2*)(g_xl + (size_t)n * CDIM + c0) = lp;
    }

    float acc[NEXP];
#pragma unroll
    for (int e = 0; e < NEXP; e++) {
        acc[e] = v.x * Wg[(c0 + 0) * NEXP + e] + v.y * Wg[(c0 + 1) * NEXP + e]
               + v.z * Wg[(c0 + 2) * NEXP + e] + v.w * Wg[(c0 + 3) * NEXP + e];
    }
#pragma unroll
    for (int off = 16; off; off >>= 1)
#pragma unroll
        for (int e = 0; e < NEXP; e++)
            acc[e] += __shfl_down_sync(0xffffffffu, acc[e], off);

    __shared__ float red[8][NEXP];
    if ((t & 31) == 0)
#pragma unroll
        for (int e = 0; e < NEXP; e++) red[t >> 5][e] = acc[e];
    __syncthreads();
    if (t == 0) {
        float l[NEXP];
#pragma unroll
        for (int e = 0; e < NEXP; e++) {
            float s = 0.f;
#pragma unroll
            for (int w = 0; w < 8; w++) s += red[w][e];   // fixed order
            l[e] = s;
        }
        float mx = l[0];
#pragma unroll
        for (int e = 1; e < NEXP; e++) mx = fmaxf(mx, l[e]);
        float p[NEXP];
#pragma unroll
        for (int e = 0; e < NEXP; e++) p[e] = expf(l[e] - mx);
        int i0 = 0;
#pragma unroll
        for (int e = 1; e < NEXP; e++) if (p[e] > p[i0]) i0 = e;
        int i1 = (i0 == 0) ? 1 : 0;
#pragma unroll
        for (int e = 0; e < NEXP; e++) if (e != i0 && p[e] > p[i1]) i1 = e;
        float s = p[i0] + p[i1];
        g_topi[2 * n]     = i0;
        g_topi[2 * n + 1] = i1;
        g_topw[2 * n]     = p[i0] / s;
        g_topw[2 * n + 1] = p[i1] / s;
    }
}

// ---------------- routing bookkeeping ----------------------------------------
__global__ void route_build_kernel() {
    __shared__ int cnt[NEXP], cur[NEXP];
    const int t = threadIdx.x;
    if (t < NEXP) cnt[t] = 0;
    __syncthreads();
    for (int i = t; i < NPAIR; i += 1024) atomicAdd(&cnt[g_topi[i]], 1);
    __syncthreads();
    if (t == 0) {
        int s = 0;
        for (int e = 0; e < NEXP; e++) {
            g_counts[e] = cnt[e];
            g_offs[e] = s; cur[e] = s; s += cnt[e];
        }
        g_offs[NEXP] = s;
    }
    __syncthreads();
    for (int i = t; i < NPAIR; i += 1024) {
        int e = g_topi[i];
        int pos = atomicAdd(&cur[e], 1);   // per-row math order-free -> deterministic
        g_rows[pos] = i >> 1;
        g_map[i]    = pos;
    }
}

// ---------------- weight fp32 -> fp16 convert ---------------------------------
__global__ void wcvt_kernel(const float* __restrict__ W1,
                            const float* __restrict__ W3,
                            const float* __restrict__ W2) {
    const int which = blockIdx.y;
    const float* src = (which == 0) ? W1 : (which == 1) ? W3 : W2;
    __half* dst = (which == 0) ? g_w1f : (which == 1) ? g_w3f : g_w2f;
    size_t i = ((size_t)blockIdx.x * blockDim.x + threadIdx.x) * 8;
    float4 a = *(const float4*)(src + i);
    float4 b = *(const float4*)(src + i + 4);
    unsigned short h[8];
    h[0] = __half_as_ushort(__float2half_rn(a.x));
    h[1] = __half_as_ushort(__float2half_rn(a.y));
    h[2] = __half_as_ushort(__float2half_rn(a.z));
    h[3] = __half_as_ushort(__float2half_rn(a.w));
    h[4] = __half_as_ushort(__float2half_rn(b.x));
    h[5] = __half_as_ushort(__float2half_rn(b.y));
    h[6] = __half_as_ushort(__float2half_rn(b.z));
    h[7] = __half_as_ushort(__float2half_rn(b.w));
    uint4 o;
    o.x = (unsigned)h[0] | ((unsigned)h[1] << 16);
    o.y = (unsigned)h[2] | ((unsigned)h[3] << 16);
    o.z = (unsigned)h[4] | ((unsigned)h[5] << 16);
    o.w = (unsigned)h[6] | ((unsigned)h[7] << 16);
    *(uint4*)(dst + i) = o;
}

// ---------------- shared GEMM params ------------------------------------------
#define TM 128
#define TK 32
#define NSTG 3
#define ASTR 40

// ======================= fused W1+W3 GEMM =====================================
#define BSTRF 72

struct SmemF {
    __half Ah[NSTG][TM][ASTR];
    __half Al[NSTG][TM][ASTR];
    __half B1[NSTG][TK][BSTRF];
    __half B3[NSTG][TK][BSTRF];
    int srow[TM];
};
#define AL_OFF  (NSTG * TM * ASTR * 2)
#define SMEMF_BYTES ((int)sizeof(SmemF))

struct FragF {
    unsigned ah[2][4], al[2][4];
    unsigned b1[4][2], b3[4][2];
};

__device__ __forceinline__ void frag_load_f(FragF& f, SmemF& S, int s, int kk,
                                            int wm, int wn, int lane) {
#pragma unroll
    for (int mh = 0; mh < 2; mh++) {
        unsigned a = sm_u32(&S.Ah[s][wm + mh * 16 + (lane & 15)][kk + (lane >> 4) * 8]);
        ldsm4(f.ah[mh], a);
        ldsm4(f.al[mh], a + AL_OFF);
    }
#pragma unroll
    for (int ng = 0; ng < 2; ng++) {
        unsigned a1 = sm_u32(&S.B1[s][kk + (lane & 15)][wn + ng * 16 + (lane >> 4) * 8]);
        unsigned r[4];
        ldsm4t(r, a1);
        f.b1[2 * ng][0] = r[0]; f.b1[2 * ng][1] = r[1];
        f.b1[2 * ng + 1][0] = r[2]; f.b1[2 * ng + 1][1] = r[3];
        unsigned a3 = sm_u32(&S.B3[s][kk + (lane & 15)][wn + ng * 16 + (lane >> 4) * 8]);
        ldsm4t(r, a3);
        f.b3[2 * ng][0] = r[0]; f.b3[2 * ng][1] = r[1];
        f.b3[2 * ng + 1][0] = r[2]; f.b3[2 * ng + 1][1] = r[3];
    }
}

__device__ __forceinline__ void frag_mma_f(float acc1[2][4][4], float acc3[2][4][4],
                                           const FragF& f) {
#pragma unroll
    for (int mh = 0; mh < 2; mh++)
#pragma unroll
        for (int nf = 0; nf < 4; nf++) mma_f16(acc1[mh][nf], f.ah[mh], f.b1[nf]);
#pragma unroll
    for (int mh = 0; mh < 2; mh++)
#pragma unroll
        for (int nf = 0; nf < 4; nf++) mma_f16(acc3[mh][nf], f.ah[mh], f.b3[nf]);
#pragma unroll
    for (int mh = 0; mh < 2; mh++)
#pragma unroll
        for (int nf = 0; nf < 4; nf++) mma_f16(acc1[mh][nf], f.al[mh], f.b1[nf]);
#pragma unroll
    for (int mh = 0; mh < 2; mh++)
#pragma unroll
        for (int nf = 0; nf < 4; nf++) mma_f16(acc3[mh][nf], f.al[mh], f.b3[nf]);
}

__global__ __launch_bounds__(256, 2) void gemm_fused13() {
    constexpr int Kd = CDIM;
    constexpr int Nd = HDIM;
    constexpr int NS = Kd / TK;
    extern __shared__ char sm_raw[];
    SmemF& S = *reinterpret_cast<SmemF*>(sm_raw);

    const int e    = blockIdx.z;
    const int cnt  = g_counts[e];
    const int row0 = blockIdx.y * TM;
    if (row0 >= cnt) return;
    const int mrows    = min(TM, cnt - row0);
    const int slotbase = g_offs[e] + row0;
    const int nt0      = blockIdx.x * 64;

    const int t = threadIdx.x;
    if (t < TM) {
        int m = min(t, mrows - 1);
        S.srow[t] = g_rows[slotbase + m];
    }
    __syncthreads();

    const int lane = t & 31;
    const int warp = t >> 5;
    const int wm = (warp & 3) * 32;
    const int wn = (warp >> 2) * 32;

    const int ar = t >> 1;
    const int ac = (t & 1) * 16;
    const size_t myrow = (size_t)S.srow[ar];
    const __half* pah = g_xh + myrow * Kd + ac;
    const __half* pal = g_xl + myrow * Kd + ac;
    const int bkr = t >> 3;          // 0..31
    const int bnc = (t & 7) * 8;     // 0..56
    const size_t boff = ((size_t)e * Kd + bkr) * Nd + nt0 + bnc;
    const __half* pb1 = g_w1f + boff;
    const __half* pb3 = g_w3f + boff;

    float acc1[2][4][4], acc3[2][4][4];
#pragma unroll
    for (int mi = 0; mi < 2; mi++)
#pragma unroll
        for (int ni = 0; ni < 4; ni++)
#pragma unroll
            for (int j = 0; j < 4; j++) { acc1[mi][ni][j] = 0.f; acc3[mi][ni][j] = 0.f; }

    auto load_stage = [&](int s, int k0) {
        unsigned sa = sm_u32(&S.Ah[s][ar][ac]);
        cp16(sa,               pah + k0);
        cp16(sa + 16,          pah + k0 + 8);
        cp16(sa + AL_OFF,      pal + k0);
        cp16(sa + AL_OFF + 16, pal + k0 + 8);
        const size_t ko = (size_t)k0 * Nd;
        cp16(sm_u32(&S.B1[s][bkr][bnc]), pb1 + ko);
        cp16(sm_u32(&S.B3[s][bkr][bnc]), pb3 + ko);
        CP_COMMIT();
    };

    load_stage(0, 0);
    load_stage(1, TK);

#pragma unroll 1
    for (int j = 0; j < NS; j++) {
        const int s = j % NSTG;
        if (j == NS - 1) { CP_WAIT0(); } else { CP_WAIT1(); }   // stage j resident
        __syncthreads();     // publish; also guards slot (j-1)%3 refill below
        if (j + 2 < NS) load_stage((j + 2) % NSTG, (j + 2) * TK);
        FragF f;
        frag_load_f(f, S, s, 0, wm, wn, lane);
        frag_mma_f(acc1, acc3, f);
        frag_load_f(f, S, s, 16, wm, wn, lane);
        frag_mma_f(acc1, acc3, f);
    }

    // epilogue: h = silu(d1) * d3 -> single fp16 plane
    const int g = lane >> 2;
    const int q = lane & 3;
#pragma unroll
    for (int mh = 0; mh < 2; mh++)
#pragma unroll
        for (int nf = 0; nf < 4; nf++) {
            int r0 = wm + mh * 16 + g;
            int c  = nt0 + wn + nf * 8 + q * 2;
#pragma unroll
            for (int half = 0; half < 2; half++) {
                int r = r0 + half * 8;
                if (r >= mrows) continue;
                size_t orow = (size_t)(slotbase + r);
                float d10 = acc1[mh][nf][2 * half], d11 = acc1[mh][nf][2 * half + 1];
                float d30 = acc3[mh][nf][2 * half], d31 = acc3[mh][nf][2 * half + 1];
                float w0 = d10 / (1.f + __expf(-d10)) * d30;
                float w1 = d11 / (1.f + __expf(-d11)) * d31;
                unsigned short h0 = __half_as_ushort(__float2half_rn(w0));
                unsigned short h1 = __half_as_ushort(__float2half_rn(w1));
                *(unsigned*)(g_hh + orow * HDIM + c) = (unsigned)h0 | ((unsigned)h1 << 16);
            }
        }
}

// ======================= W2 GEMM (hidden -> y, single-term fp16) ==============
#define TN2 128
#define BSTR2 136

struct Smem2 {
    __half Ah[NSTG][TM][ASTR];
    __half B[NSTG][TK][BSTR2];
    int srow[TM];
};
#define SMEM2_BYTES ((int)sizeof(Smem2))

struct Frag2 {
    unsigned ah[2][4];
    unsigned bh[8][2];
};

__device__ __forceinline__ void frag_load_2(Frag2& f, Smem2& S, int s, int kk,
                                            int wm, int wn, int lane) {
#pragma unroll
    for (int mh = 0; mh < 2; mh++) {
        unsigned a = sm_u32(&S.Ah[s][wm + mh * 16 + (lane & 15)][kk + (lane >> 4) * 8]);
        ldsm4(f.ah[mh], a);
    }
#pragma unroll
    for (int ng = 0; ng < 4; ng++) {
        unsigned a = sm_u32(&S.B[s][kk + (lane & 15)][wn + ng * 16 + (lane >> 4) * 8]);
        unsigned r[4];
        ldsm4t(r, a);
        f.bh[2 * ng][0] = r[0]; f.bh[2 * ng][1] = r[1];
        f.bh[2 * ng + 1][0] = r[2]; f.bh[2 * ng + 1][1] = r[3];
    }
}

__device__ __forceinline__ void frag_mma_2(float acc[2][8][4], const Frag2& f) {
#pragma unroll
    for (int mh = 0; mh < 2; mh++)
#pragma unroll
        for (int nf = 0; nf < 8; nf++) mma_f16(acc[mh][nf], f.ah[mh], f.bh[nf]);
}

__global__ __launch_bounds__(256, 2) void gemm_w2() {
    constexpr int Kd = HDIM;
    constexpr int Nd = CDIM;
    constexpr int NS = Kd / TK;
    extern __shared__ char sm_raw[];
    Smem2& S = *reinterpret_cast<Smem2*>(sm_raw);

    const int e    = blockIdx.z;
    const int cnt  = g_counts[e];
    const int row0 = blockIdx.y * TM;
    if (row0 >= cnt) return;
    const int mrows    = min(TM, cnt - row0);
    const int slotbase = g_offs[e] + row0;
    const int nt0      = blockIdx.x * TN2;

    const int t = threadIdx.x;
    if (t < TM) S.srow[t] = slotbase + min(t, mrows - 1);
    __syncthreads();

    const int lane = t & 31;
    const int warp = t >> 5;
    const int wm = (warp & 3) * 32;
    const int wn = (warp >> 2) * 64;

    const int ar = t >> 1;
    const int ac = (t & 1) * 16;
    const size_t myrow = (size_t)S.srow[ar];
    const __half* pah = g_hh + myrow * Kd + ac;
    const int bkr = t >> 3;
    const int bnc = (t & 7) * 16;
    const __half* pb = g_w2f + ((size_t)e * Kd + bkr) * Nd + nt0 + bnc;

    float acc[2][8][4];
#pragma unroll
    for (int mi = 0; mi < 2; mi++)
#pragma unroll
        for (int ni = 0; ni < 8; ni++)
#pragma unroll
            for (int j = 0; j < 4; j++) acc[mi][ni][j] = 0.f;

    auto load_stage = [&](int s, int k0) {
        unsigned sa = sm_u32(&S.Ah[s][ar][ac]);
        cp16(sa,      pah + k0);
        cp16(sa + 16, pah + k0 + 8);
        unsigned sb = sm_u32(&S.B[s][bkr][bnc]);
        const __half* bh = pb + (size_t)k0 * Nd;
        cp16(sb,      bh);
        cp16(sb + 16, bh + 8);
        CP_COMMIT();
    };

    load_stage(0, 0);
    load_stage(1, TK);

#pragma unroll 1
    for (int j = 0; j < NS; j++) {
        const int s = j % NSTG;
        if (j == NS - 1) { CP_WAIT0(); } else { CP_WAIT1(); }
        __syncthreads();
        if (j + 2 < NS) load_stage((j + 2) % NSTG, (j + 2) * TK);
        Frag2 f;
        frag_load_2(f, S, s, 0, wm, wn, lane);
        frag_mma_2(acc, f);
        frag_load_2(f, S, s, 16, wm, wn, lane);
        frag_mma_2(acc, f);
    }

    const int g = lane >> 2;
    const int q = lane & 3;
#pragma unroll
    for (int mh = 0; mh < 2; mh++)
#pragma unroll
        for (int nf = 0; nf < 8; nf++) {
            int r0 = wm + mh * 16 + g;
            int c  = nt0 + wn + nf * 8 + q * 2;
#pragma unroll
            for (int half = 0; half < 2; half++) {
                int r = r0 + half * 8;
                if (r >= mrows) continue;
                size_t orow = (size_t)(slotbase + r);
                float* p = g_y + orow * CDIM + c;
                p[0] = acc[mh][nf][2 * half];
                p[1] = acc[mh][nf][2 * half + 1];
            }
        }
}

// ---------------- final gather-combine --------------------------------------
__global__ void combine_kernel(float* __restrict__ out) {
    int idx = blockIdx.x * blockDim.x + threadIdx.x;
    int n  = idx >> 8;
    int c4 = (idx & 255) << 2;
    int p0 = g_map[2 * n], p1 = g_map[2 * n + 1];
    float w0 = g_topw[2 * n], w1 = g_topw[2 * n + 1];
    float4 y0 = *(const float4*)(g_y + (size_t)p0 * CDIM + c4);
    float4 y1 = *(const float4*)(g_y + (size_t)p1 * CDIM + c4);
    float4 r;
    r.x = w0 * y0.x + w1 * y1.x;
    r.y = w0 * y0.y + w1 * y1.y;
    r.z = w0 * y0.z + w1 * y1.z;
    r.w = w0 * y0.w + w1 * y1.w;
    *(float4*)(out + (size_t)n * CDIM + c4) = r;
}

// ---------------- launch ------------------------------------------------------
extern "C" void kernel_launch(void* const* d_in, const int* in_sizes, int n_in,
                              void* d_out, int out_size) {
    const float* x  = (const float*)d_in[0];
    const float* Wg = (const float*)d_in[1];
    const float* W1 = (const float*)d_in[2];
    const float* W3 = (const float*)d_in[3];
    const float* W2 = (const float*)d_in[4];
    float* out = (float*)d_out;

    cudaFuncSetAttribute(gemm_fused13, cudaFuncAttributeMaxDynamicSharedMemorySize, SMEMF_BYTES);
    cudaFuncSetAttribute(gemm_w2, cudaFuncAttributeMaxDynamicSharedMemorySize, SMEM2_BYTES);

    const size_t WELEMS = (size_t)NEXP * CDIM * HDIM;

    // launch index 3 = gemm_fused13, index 4 = gemm_w2 (ncu captures index 3)
    wcvt_kernel<<<dim3((unsigned)(WELEMS / 8 / 256), 3), 256>>>(W1, W3, W2);  // 0
    router_kernel<<<NTOK, 256>>>(x, Wg);                                      // 1
    route_build_kernel<<<1, 1024>>>();                                        // 2
    gemm_fused13<<<dim3(HDIM / 64, NTOK / TM, NEXP), 256, SMEMF_BYTES>>>();   // 3
    gemm_w2<<<dim3(CDIM / TN2, NTOK / TM, NEXP), 256, SMEM2_BYTES>>>();       // 4
    combine_kernel<<<(NTOK * (CDIM / 4)) / 256, 256>>>(out);                  // 5
}

// round 12
// speedup vs baseline: 2.6589x; 1.3175x over previous
#include <cuda_runtime.h>
#include <cuda_fp16.h>
#include <math.h>

#define NTOK 4096
#define CDIM 1024
#define HDIM 4096
#define NEXP 8
#define NPAIR (NTOK * 2)

// ---------------- scratch (device globals) -----------------------------------
__device__ int   g_counts[NEXP];
__device__ int   g_offs[NEXP + 1];
__device__ int   g_topi[NPAIR];
__device__ float g_topw[NPAIR];
__device__ int   g_rows[NPAIR];
__device__ int   g_map[NPAIR];
__device__ __half g_xh[(size_t)NTOK * CDIM];     // x (single fp16 plane)
__device__ __half g_hh[(size_t)NPAIR * HDIM];    // hidden (single fp16 plane)
__device__ float g_y [(size_t)NPAIR * CDIM];
__device__ __half g_w1f[(size_t)NEXP * CDIM * HDIM];
__device__ __half g_w3f[(size_t)NEXP * CDIM * HDIM];
__device__ __half g_w2f[(size_t)NEXP * HDIM * CDIM];

// ---------------- helpers -----------------------------------------------------
__device__ __forceinline__ unsigned sm_u32(const void* p) {
    return (unsigned)__cvta_generic_to_shared(p);
}
__device__ __forceinline__ void cp16(unsigned s, const void* g) {
    asm volatile("cp.async.cg.shared.global [%0], [%1], 16;\n" :: "r"(s), "l"(g));
}
#define CP_COMMIT() asm volatile("cp.async.commit_group;" ::: "memory")
#define CP_WAIT1()  asm volatile("cp.async.wait_group 1;" ::: "memory")
#define CP_WAIT0()  asm volatile("cp.async.wait_group 0;" ::: "memory")
__device__ __forceinline__ void ldsm4(unsigned* r, unsigned a) {
    asm volatile("ldmatrix.sync.aligned.m8n8.x4.shared.b16 {%0,%1,%2,%3}, [%4];"
                 : "=r"(r[0]), "=r"(r[1]), "=r"(r[2]), "=r"(r[3]) : "r"(a));
}
__device__ __forceinline__ void ldsm4t(unsigned* r, unsigned a) {
    asm volatile("ldmatrix.sync.aligned.m8n8.x4.trans.shared.b16 {%0,%1,%2,%3}, [%4];"
                 : "=r"(r[0]), "=r"(r[1]), "=r"(r[2]), "=r"(r[3]) : "r"(a));
}
__device__ __forceinline__ void mma_f16(float* d, const unsigned* a, const unsigned* b) {
    asm volatile(
        "mma.sync.aligned.m16n8k16.row.col.f32.f16.f16.f32 "
        "{%0,%1,%2,%3}, {%4,%5,%6,%7}, {%8,%9}, {%0,%1,%2,%3};\n"
        : "+f"(d[0]), "+f"(d[1]), "+f"(d[2]), "+f"(d[3])
        : "r"(a[0]), "r"(a[1]), "r"(a[2]), "r"(a[3]), "r"(b[0]), "r"(b[1]));
}

// ---------------- router (fused with x fp16 convert) --------------------------
__global__ void router_kernel(const float* __restrict__ x,
                              const float* __restrict__ Wg) {
    const int n = blockIdx.x;
    const int t = threadIdx.x;
    const int c0 = t * 4;
    const float4 v = *(const float4*)(x + (size_t)n * CDIM + c0);

    {
        unsigned short h0 = __half_as_ushort(__float2half_rn(v.x));
        unsigned short h1 = __half_as_ushort(__float2half_rn(v.y));
        unsigned short h2 = __half_as_ushort(__float2half_rn(v.z));
        unsigned short h3 = __half_as_ushort(__float2half_rn(v.w));
        uint2 hp;
        hp.x = (unsigned)h0 | ((unsigned)h1 << 16);
        hp.y = (unsigned)h2 | ((unsigned)h3 << 16);
        *(uint2*)(g_xh + (size_t)n * CDIM + c0) = hp;
    }

    float acc[NEXP];
#pragma unroll
    for (int e = 0; e < NEXP; e++) {
        acc[e] = v.x * Wg[(c0 + 0) * NEXP + e] + v.y * Wg[(c0 + 1) * NEXP + e]
               + v.z * Wg[(c0 + 2) * NEXP + e] + v.w * Wg[(c0 + 3) * NEXP + e];
    }
#pragma unroll
    for (int off = 16; off; off >>= 1)
#pragma unroll
        for (int e = 0; e < NEXP; e++)
            acc[e] += __shfl_down_sync(0xffffffffu, acc[e], off);

    __shared__ float red[8][NEXP];
    if ((t & 31) == 0)
#pragma unroll
        for (int e = 0; e < NEXP; e++) red[t >> 5][e] = acc[e];
    __syncthreads();
    if (t == 0) {
        float l[NEXP];
#pragma unroll
        for (int e = 0; e < NEXP; e++) {
            float s = 0.f;
#pragma unroll
            for (int w = 0; w < 8; w++) s += red[w][e];   // fixed order
            l[e] = s;
        }
        float mx = l[0];
#pragma unroll
        for (int e = 1; e < NEXP; e++) mx = fmaxf(mx, l[e]);
        float p[NEXP];
#pragma unroll
        for (int e = 0; e < NEXP; e++) p[e] = expf(l[e] - mx);
        int i0 = 0;
#pragma unroll
        for (int e = 1; e < NEXP; e++) if (p[e] > p[i0]) i0 = e;
        int i1 = (i0 == 0) ? 1 : 0;
#pragma unroll
        for (int e = 0; e < NEXP; e++) if (e != i0 && p[e] > p[i1]) i1 = e;
        float s = p[i0] + p[i1];
        g_topi[2 * n]     = i0;
        g_topi[2 * n + 1] = i1;
        g_topw[2 * n]     = p[i0] / s;
        g_topw[2 * n + 1] = p[i1] / s;
    }
}

// ---------------- routing bookkeeping ----------------------------------------
__global__ void route_build_kernel() {
    __shared__ int cnt[NEXP], cur[NEXP];
    const int t = threadIdx.x;
    if (t < NEXP) cnt[t] = 0;
    __syncthreads();
    for (int i = t; i < NPAIR; i += 1024) atomicAdd(&cnt[g_topi[i]], 1);
    __syncthreads();
    if (t == 0) {
        int s = 0;
        for (int e = 0; e < NEXP; e++) {
            g_counts[e] = cnt[e];
            g_offs[e] = s; cur[e] = s; s += cnt[e];
        }
        g_offs[NEXP] = s;
    }
    __syncthreads();
    for (int i = t; i < NPAIR; i += 1024) {
        int e = g_topi[i];
        int pos = atomicAdd(&cur[e], 1);   // per-row math order-free -> deterministic
        g_rows[pos] = i >> 1;
        g_map[i]    = pos;
    }
}

// ---------------- weight fp32 -> fp16 convert ---------------------------------
__global__ void wcvt_kernel(const float* __restrict__ W1,
                            const float* __restrict__ W3,
                            const float* __restrict__ W2) {
    const int which = blockIdx.y;
    const float* src = (which == 0) ? W1 : (which == 1) ? W3 : W2;
    __half* dst = (which == 0) ? g_w1f : (which == 1) ? g_w3f : g_w2f;
    size_t i = ((size_t)blockIdx.x * blockDim.x + threadIdx.x) * 8;
    float4 a = *(const float4*)(src + i);
    float4 b = *(const float4*)(src + i + 4);
    unsigned short h[8];
    h[0] = __half_as_ushort(__float2half_rn(a.x));
    h[1] = __half_as_ushort(__float2half_rn(a.y));
    h[2] = __half_as_ushort(__float2half_rn(a.z));
    h[3] = __half_as_ushort(__float2half_rn(a.w));
    h[4] = __half_as_ushort(__float2half_rn(b.x));
    h[5] = __half_as_ushort(__float2half_rn(b.y));
    h[6] = __half_as_ushort(__float2half_rn(b.z));
    h[7] = __half_as_ushort(__float2half_rn(b.w));
    uint4 o;
    o.x = (unsigned)h[0] | ((unsigned)h[1] << 16);
    o.y = (unsigned)h[2] | ((unsigned)h[3] << 16);
    o.z = (unsigned)h[4] | ((unsigned)h[5] << 16);
    o.w = (unsigned)h[6] | ((unsigned)h[7] << 16);
    *(uint4*)(dst + i) = o;
}

// ---------------- shared GEMM params ------------------------------------------
#define TM 128
#define TK 32
#define NSTG 3
#define ASTR 40

// ======================= fused W1+W3 GEMM (1-term fp16) =======================
#define BSTRF 72

struct SmemF {
    __half A[NSTG][TM][ASTR];
    __half B1[NSTG][TK][BSTRF];
    __half B3[NSTG][TK][BSTRF];
    int srow[TM];
};
#define SMEMF_BYTES ((int)sizeof(SmemF))

struct FragF {
    unsigned ah[2][4];
    unsigned b1[4][2], b3[4][2];
};

__device__ __forceinline__ void frag_load_f(FragF& f, SmemF& S, int s, int kk,
                                            int wm, int wn, int lane) {
#pragma unroll
    for (int mh = 0; mh < 2; mh++) {
        unsigned a = sm_u32(&S.A[s][wm + mh * 16 + (lane & 15)][kk + (lane >> 4) * 8]);
        ldsm4(f.ah[mh], a);
    }
#pragma unroll
    for (int ng = 0; ng < 2; ng++) {
        unsigned a1 = sm_u32(&S.B1[s][kk + (lane & 15)][wn + ng * 16 + (lane >> 4) * 8]);
        unsigned r[4];
        ldsm4t(r, a1);
        f.b1[2 * ng][0] = r[0]; f.b1[2 * ng][1] = r[1];
        f.b1[2 * ng + 1][0] = r[2]; f.b1[2 * ng + 1][1] = r[3];
        unsigned a3 = sm_u32(&S.B3[s][kk + (lane & 15)][wn + ng * 16 + (lane >> 4) * 8]);
        ldsm4t(r, a3);
        f.b3[2 * ng][0] = r[0]; f.b3[2 * ng][1] = r[1];
        f.b3[2 * ng + 1][0] = r[2]; f.b3[2 * ng + 1][1] = r[3];
    }
}

__device__ __forceinline__ void frag_mma_f(float acc1[2][4][4], float acc3[2][4][4],
                                           const FragF& f) {
#pragma unroll
    for (int mh = 0; mh < 2; mh++)
#pragma unroll
        for (int nf = 0; nf < 4; nf++) mma_f16(acc1[mh][nf], f.ah[mh], f.b1[nf]);
#pragma unroll
    for (int mh = 0; mh < 2; mh++)
#pragma unroll
        for (int nf = 0; nf < 4; nf++) mma_f16(acc3[mh][nf], f.ah[mh], f.b3[nf]);
}

__global__ __launch_bounds__(256, 2) void gemm_fused13() {
    constexpr int Kd = CDIM;
    constexpr int Nd = HDIM;
    constexpr int NS = Kd / TK;
    extern __shared__ char sm_raw[];
    SmemF& S = *reinterpret_cast<SmemF*>(sm_raw);

    const int e    = blockIdx.z;
    const int cnt  = g_counts[e];
    const int row0 = blockIdx.y * TM;
    if (row0 >= cnt) return;
    const int mrows    = min(TM, cnt - row0);
    const int slotbase = g_offs[e] + row0;
    const int nt0      = blockIdx.x * 64;

    const int t = threadIdx.x;
    if (t < TM) {
        int m = min(t, mrows - 1);
        S.srow[t] = g_rows[slotbase + m];
    }
    __syncthreads();

    const int lane = t & 31;
    const int warp = t >> 5;
    const int wm = (warp & 3) * 32;
    const int wn = (warp >> 2) * 32;

    const int ar = t >> 1;
    const int ac = (t & 1) * 16;
    const size_t myrow = (size_t)S.srow[ar];
    const __half* pah = g_xh + myrow * Kd + ac;
    const int bkr = t >> 3;          // 0..31
    const int bnc = (t & 7) * 8;     // 0..56
    const size_t boff = ((size_t)e * Kd + bkr) * Nd + nt0 + bnc;
    const __half* pb1 = g_w1f + boff;
    const __half* pb3 = g_w3f + boff;

    float acc1[2][4][4], acc3[2][4][4];
#pragma unroll
    for (int mi = 0; mi < 2; mi++)
#pragma unroll
        for (int ni = 0; ni < 4; ni++)
#pragma unroll
            for (int j = 0; j < 4; j++) { acc1[mi][ni][j] = 0.f; acc3[mi][ni][j] = 0.f; }

    auto load_stage = [&](int s, int k0) {
        unsigned sa = sm_u32(&S.A[s][ar][ac]);
        cp16(sa,      pah + k0);
        cp16(sa + 16, pah + k0 + 8);
        const size_t ko = (size_t)k0 * Nd;
        cp16(sm_u32(&S.B1[s][bkr][bnc]), pb1 + ko);
        cp16(sm_u32(&S.B3[s][bkr][bnc]), pb3 + ko);
        CP_COMMIT();
    };

    load_stage(0, 0);
    load_stage(1, TK);

#pragma unroll 1
    for (int j = 0; j < NS; j++) {
        const int s = j % NSTG;
        if (j == NS - 1) { CP_WAIT0(); } else { CP_WAIT1(); }   // stage j resident
        __syncthreads();     // publish; also guards slot (j-1)%3 refill below
        if (j + 2 < NS) load_stage((j + 2) % NSTG, (j + 2) * TK);
        FragF f;
        frag_load_f(f, S, s, 0, wm, wn, lane);
        frag_mma_f(acc1, acc3, f);
        frag_load_f(f, S, s, 16, wm, wn, lane);
        frag_mma_f(acc1, acc3, f);
    }

    // epilogue: h = silu(d1) * d3 -> single fp16 plane
    const int g = lane >> 2;
    const int q = lane & 3;
#pragma unroll
    for (int mh = 0; mh < 2; mh++)
#pragma unroll
        for (int nf = 0; nf < 4; nf++) {
            int r0 = wm + mh * 16 + g;
            int c  = nt0 + wn + nf * 8 + q * 2;
#pragma unroll
            for (int half = 0; half < 2; half++) {
                int r = r0 + half * 8;
                if (r >= mrows) continue;
                size_t orow = (size_t)(slotbase + r);
                float d10 = acc1[mh][nf][2 * half], d11 = acc1[mh][nf][2 * half + 1];
                float d30 = acc3[mh][nf][2 * half], d31 = acc3[mh][nf][2 * half + 1];
                float w0 = d10 / (1.f + __expf(-d10)) * d30;
                float w1 = d11 / (1.f + __expf(-d11)) * d31;
                unsigned short h0 = __half_as_ushort(__float2half_rn(w0));
                unsigned short h1 = __half_as_ushort(__float2half_rn(w1));
                *(unsigned*)(g_hh + orow * HDIM + c) = (unsigned)h0 | ((unsigned)h1 << 16);
            }
        }
}

// ======================= W2 GEMM (hidden -> y, single-term fp16) ==============
#define TN2 128
#define BSTR2 136

struct Smem2 {
    __half Ah[NSTG][TM][ASTR];
    __half B[NSTG][TK][BSTR2];
    int srow[TM];
};
#define SMEM2_BYTES ((int)sizeof(Smem2))

struct Frag2 {
    unsigned ah[2][4];
    unsigned bh[8][2];
};

__device__ __forceinline__ void frag_load_2(Frag2& f, Smem2& S, int s, int kk,
                                            int wm, int wn, int lane) {
#pragma unroll
    for (int mh = 0; mh < 2; mh++) {
        unsigned a = sm_u32(&S.Ah[s][wm + mh * 16 + (lane & 15)][kk + (lane >> 4) * 8]);
        ldsm4(f.ah[mh], a);
    }
#pragma unroll
    for (int ng = 0; ng < 4; ng++) {
        unsigned a = sm_u32(&S.B[s][kk + (lane & 15)][wn + ng * 16 + (lane >> 4) * 8]);
        unsigned r[4];
        ldsm4t(r, a);
        f.bh[2 * ng][0] = r[0]; f.bh[2 * ng][1] = r[1];
        f.bh[2 * ng + 1][0] = r[2]; f.bh[2 * ng + 1][1] = r[3];
    }
}

__device__ __forceinline__ void frag_mma_2(float acc[2][8][4], const Frag2& f) {
#pragma unroll
    for (int mh = 0; mh < 2; mh++)
#pragma unroll
        for (int nf = 0; nf < 8; nf++) mma_f16(acc[mh][nf], f.ah[mh], f.bh[nf]);
}

__global__ __launch_bounds__(256, 2) void gemm_w2() {
    constexpr int Kd = HDIM;
    constexpr int Nd = CDIM;
    constexpr int NS = Kd / TK;
    extern __shared__ char sm_raw[];
    Smem2& S = *reinterpret_cast<Smem2*>(sm_raw);

    const int e    = blockIdx.z;
    const int cnt  = g_counts[e];
    const int row0 = blockIdx.y * TM;
    if (row0 >= cnt) return;
    const int mrows    = min(TM, cnt - row0);
    const int slotbase = g_offs[e] + row0;
    const int nt0      = blockIdx.x * TN2;

    const int t = threadIdx.x;
    if (t < TM) S.srow[t] = slotbase + min(t, mrows - 1);
    __syncthreads();

    const int lane = t & 31;
    const int warp = t >> 5;
    const int wm = (warp & 3) * 32;
    const int wn = (warp >> 2) * 64;

    const int ar = t >> 1;
    const int ac = (t & 1) * 16;
    const size_t myrow = (size_t)S.srow[ar];
    const __half* pah = g_hh + myrow * Kd + ac;
    const int bkr = t >> 3;
    const int bnc = (t & 7) * 16;
    const __half* pb = g_w2f + ((size_t)e * Kd + bkr) * Nd + nt0 + bnc;

    float acc[2][8][4];
#pragma unroll
    for (int mi = 0; mi < 2; mi++)
#pragma unroll
        for (int ni = 0; ni < 8; ni++)
#pragma unroll
            for (int j = 0; j < 4; j++) acc[mi][ni][j] = 0.f;

    auto load_stage = [&](int s, int k0) {
        unsigned sa = sm_u32(&S.Ah[s][ar][ac]);
        cp16(sa,      pah + k0);
        cp16(sa + 16, pah + k0 + 8);
        unsigned sb = sm_u32(&S.B[s][bkr][bnc]);
        const __half* bh = pb + (size_t)k0 * Nd;
        cp16(sb,      bh);
        cp16(sb + 16, bh + 8);
        CP_COMMIT();
    };

    load_stage(0, 0);
    load_stage(1, TK);

#pragma unroll 1
    for (int j = 0; j < NS; j++) {
        const int s = j % NSTG;
        if (j == NS - 1) { CP_WAIT0(); } else { CP_WAIT1(); }
        __syncthreads();
        if (j + 2 < NS) load_stage((j + 2) % NSTG, (j + 2) * TK);
        Frag2 f;
        frag_load_2(f, S, s, 0, wm, wn, lane);
        frag_mma_2(acc, f);
        frag_load_2(f, S, s, 16, wm, wn, lane);
        frag_mma_2(acc, f);
    }

    const int g = lane >> 2;
    const int q = lane & 3;
#pragma unroll
    for (int mh = 0; mh < 2; mh++)
#pragma unroll
        for (int nf = 0; nf < 8; nf++) {
            int r0 = wm + mh * 16 + g;
            int c  = nt0 + wn + nf * 8 + q * 2;
#pragma unroll
            for (int half = 0; half < 2; half++) {
                int r = r0 + half * 8;
                if (r >= mrows) continue;
                size_t orow = (size_t)(slotbase + r);
                float* p = g_y + orow * CDIM + c;
                p[0] = acc[mh][nf][2 * half];
                p[1] = acc[mh][nf][2 * half + 1];
            }
        }
}

// ---------------- final gather-combine --------------------------------------
__global__ void combine_kernel(float* __restrict__ out) {
    int idx = blockIdx.x * blockDim.x + threadIdx.x;
    int n  = idx >> 8;
    int c4 = (idx & 255) << 2;
    int p0 = g_map[2 * n], p1 = g_map[2 * n + 1];
    float w0 = g_topw[2 * n], w1 = g_topw[2 * n + 1];
    float4 y0 = *(const float4*)(g_y + (size_t)p0 * CDIM + c4);
    float4 y1 = *(const float4*)(g_y + (size_t)p1 * CDIM + c4);
    float4 r;
    r.x = w0 * y0.x + w1 * y1.x;
    r.y = w0 * y0.y + w1 * y1.y;
    r.z = w0 * y0.z + w1 * y1.z;
    r.w = w0 * y0.w + w1 * y1.w;
    *(float4*)(out + (size_t)n * CDIM + c4) = r;
}

// ---------------- launch ------------------------------------------------------
extern "C" void kernel_launch(void* const* d_in, const int* in_sizes, int n_in,
                              void* d_out, int out_size) {
    const float* x  = (const float*)d_in[0];
    const float* Wg = (const float*)d_in[1];
    const float* W1 = (const float*)d_in[2];
    const float* W3 = (const float*)d_in[3];
    const float* W2 = (const float*)d_in[4];
    float* out = (float*)d_out;

    cudaFuncSetAttribute(gemm_fused13, cudaFuncAttributeMaxDynamicSharedMemorySize, SMEMF_BYTES);
    cudaFuncSetAttribute(gemm_w2, cudaFuncAttributeMaxDynamicSharedMemorySize, SMEM2_BYTES);

    const size_t WELEMS = (size_t)NEXP * CDIM * HDIM;

    // launch index 3 = gemm_fused13, index 4 = gemm_w2 (ncu captures index 3)
    wcvt_kernel<<<dim3((unsigned)(WELEMS / 8 / 256), 3), 256>>>(W1, W3, W2);  // 0
    router_kernel<<<NTOK, 256>>>(x, Wg);                                      // 1
    route_build_kernel<<<1, 1024>>>();                                        // 2
    gemm_fused13<<<dim3(HDIM / 64, NTOK / TM, NEXP), 256, SMEMF_BYTES>>>();   // 3
    gemm_w2<<<dim3(CDIM / TN2, NTOK / TM, NEXP), 256, SMEM2_BYTES>>>();       // 4
    combine_kernel<<<(NTOK * (CDIM / 4)) / 256, 256>>>(out);                  // 5
}